// round 7
// baseline (speedup 1.0000x reference)
#include <cuda_runtime.h>
#include <cuda_fp16.h>
#include <cstdint>

#define NN 131072
#define DD 128
#define LL 16
#define PP 8192
#define KK 8
#define PKE (PP*KK)
#define LEVE (LL-1)
#define CH 64            // CTAs per chain
#define NTB (NN/128)     // 1024 gemm blocks in NT kernels

// ---------------- scratch (static device globals; no allocation) ----------------
__device__ float  g_h[(size_t)NN*DD];
__device__ float  g_hid[(size_t)NN*DD];
__device__ __half g_Mf[2*PP*DD];
__device__ __half g_Mb[2*PP*DD];
__device__ int    g_cnt[LEVE*PP];
__device__ int    g_rp[LEVE*(PP+1)];
__device__ int    g_fill[LEVE*PP];
__device__ int    g_col[LEVE*PKE];
__device__ unsigned g_bars[2];

#define A_FRAG_SZ (4*16*132)          // 8448 words
#define W_FRAG_SZ (16*16*66)          // 16896 words
__device__ unsigned g_wf[6*W_FRAG_SZ];   // 0 f_pre, 1 f_upd, 2 b_pre, 3 b_upd, 4 nt_w1, 5 nt_w2

// ---------------- tf32 / mma helpers ----------------
__device__ __forceinline__ unsigned tf32c(float f) {
    unsigned r;
    asm("cvt.rna.tf32.f32 %0, %1;" : "=r"(r) : "f"(f));
    return r;
}
__device__ __forceinline__ void mma8(float* d, const unsigned* a, const unsigned* b) {
    asm("mma.sync.aligned.m16n8k8.row.col.f32.tf32.tf32.f32 "
        "{%0,%1,%2,%3},{%4,%5,%6,%7},{%8,%9},{%0,%1,%2,%3};"
        : "+f"(d[0]), "+f"(d[1]), "+f"(d[2]), "+f"(d[3])
        : "r"(a[0]), "r"(a[1]), "r"(a[2]), "r"(a[3]), "r"(b[0]), "r"(b[1]));
}

__device__ __forceinline__ void frag_storeA(unsigned* sA, int r, int c4, float4 v) {
    unsigned* p = sA + (((r>>4)*16 + (c4>>1))*132) + ((r&7)*16) + ((c4&1)*2) + ((r&15)>>3);
    p[0] = tf32c(v.x); p[4] = tf32c(v.y); p[8] = tf32c(v.z); p[12] = tf32c(v.w);
}
// scalar element store into A-fragment layout (r in [0,64), k in [0,128))
__device__ __forceinline__ void frag_store1(unsigned* sA, int r, int k, float v) {
    sA[(((r>>4)*16 + (k>>3))*132) + ((r&7)*16) + ((k&3)*4) + (((k>>2)&1)*2) + ((r&15)>>3)] = tf32c(v);
}

// ---------------- build W fragments once + zero counters/barriers ----------------
__global__ void build_wfrag(const float* w0, const float* w1, const float* w2,
                            const float* w3, const float* w4, const float* w5) {
    const float* W;
    switch (blockIdx.x) {
        case 0: W = w0; break; case 1: W = w1; break; case 2: W = w2; break;
        case 3: W = w3; break; case 4: W = w4; break; default: W = w5; break;
    }
    unsigned* dst = g_wf + (size_t)blockIdx.x * W_FRAG_SZ;
    const int tid = threadIdx.x;
    #pragma unroll
    for (int it = 0; it < 16; ++it) {
        const int idx = tid + 256*it;
        const int k = idx >> 5, c4 = idx & 31;
        const float4 v = ((const float4*)W)[idx];
        unsigned* p = dst + (((c4>>1)*16 + (k>>3))*66) + ((c4&1)*32) + ((k&3)*2) + ((k>>2)&1);
        p[0] = tf32c(v.x); p[8] = tf32c(v.y); p[16] = tf32c(v.z); p[24] = tf32c(v.w);
    }
    for (int i = blockIdx.x*256 + tid; i < LEVE*PP; i += 6*256) g_cnt[i] = 0;
    if (blockIdx.x == 0 && tid < 2) g_bars[tid] = 0;
}

// ---------------- GEMM core: 64x128 tile, 8 warps (wm in [0,2), wn in [0,4)) ----------------
__device__ __forceinline__ void gemm_core(const unsigned* __restrict__ sA,
                                          const unsigned* __restrict__ sW,
                                          int wm, int wn, int lane,
                                          float acc[2][4][4]) {
    #pragma unroll
    for (int i = 0; i < 2; ++i)
        #pragma unroll
        for (int j = 0; j < 4; ++j)
            #pragma unroll
            for (int q = 0; q < 4; ++q) acc[i][j][q] = 0.f;
    #pragma unroll
    for (int kb = 0; kb < 16; ++kb) {
        unsigned a[2][4];
        #pragma unroll
        for (int i = 0; i < 2; ++i) {
            const uint4 v = *(const uint4*)(sA + (((wm*2+i)*16 + kb)*132) + lane*4);
            a[i][0] = v.x; a[i][1] = v.y; a[i][2] = v.z; a[i][3] = v.w;
        }
        unsigned b[4][2];
        #pragma unroll
        for (int j = 0; j < 4; ++j) {
            const uint2 v = *(const uint2*)(sW + (((wn*4+j)*16 + kb)*66) + lane*2);
            b[j][0] = v.x; b[j][1] = v.y;
        }
        #pragma unroll
        for (int i = 0; i < 2; ++i)
            #pragma unroll
            for (int j = 0; j < 4; ++j)
                mma8(acc[i][j], a[i], b[j]);
    }
}

// ---------------- node transform GEMM (+ piggybacked CSR work) ----------------
#define NT_SMEM ((W_FRAG_SZ + A_FRAG_SZ + 128) * 4)

template<int EPI, int EXTRA>
__global__ __launch_bounds__(256, 2) void ntgemm(
    const float* __restrict__ A, const unsigned* __restrict__ wfrag,
    const float* __restrict__ bias, float* __restrict__ Out,
    const int* __restrict__ src)
{
    extern __shared__ unsigned sm[];
    const int tid = threadIdx.x;

    if (EXTRA == 1 && blockIdx.x >= NTB) {
        const int b = blockIdx.x - NTB;
        const int tot = LEVE*PKE;
        for (int e = b*256 + tid; e < tot; e += 64*256)
            atomicAdd(&g_cnt[(e >> 16)*PP + src[e]], 1);
        return;
    }
    if (EXTRA == 2 && blockIdx.x >= NTB) {
        const int lvl = blockIdx.x - NTB;
        const int base = lvl*PP;
        int c[32]; int sum = 0;
        #pragma unroll
        for (int j = 0; j < 32; ++j) { c[j] = g_cnt[base + tid*32 + j]; sum += c[j]; }
        int* sh = (int*)sm;
        sh[tid] = sum; __syncthreads();
        for (int d = 1; d < 256; d <<= 1) {
            int v = (tid >= d) ? sh[tid-d] : 0;
            __syncthreads();
            sh[tid] += v;
            __syncthreads();
        }
        int off = sh[tid] - sum;
        int* rpl = g_rp + lvl*(PP+1);
        #pragma unroll
        for (int j = 0; j < 32; ++j) {
            const int idx = tid*32 + j;
            rpl[idx] = off; g_fill[base + idx] = off; off += c[j];
        }
        if (tid == 255) rpl[PP] = off;
        return;
    }

    unsigned* sW = sm;
    unsigned* sA = sm + W_FRAG_SZ;
    float*    sB = (float*)(sm + W_FRAG_SZ + A_FRAG_SZ);
    const int lane = tid & 31, w = tid >> 5;
    const int wm = w >> 2, wn = w & 3;
    const int g = lane >> 2, t = lane & 3;
    const int r0 = blockIdx.x * 128;

    for (int i = tid; i < W_FRAG_SZ/4; i += 256)
        ((uint4*)sW)[i] = ((const uint4*)wfrag)[i];
    if (tid < 32) ((float4*)sB)[tid] = ((const float4*)bias)[tid];
    __syncthreads();

    for (int sub = 0; sub < 2; ++sub) {
        #pragma unroll
        for (int it = 0; it < 8; ++it) {
            const int idx = tid + 256*it;
            const int r = idx >> 5, c4 = idx & 31;
            frag_storeA(sA, r, c4,
                *(const float4*)(A + (size_t)(r0 + sub*64 + r)*128 + c4*4));
        }
        __syncthreads();
        float acc[2][4][4];
        gemm_core(sA, sW, wm, wn, lane, acc);
        #pragma unroll
        for (int i = 0; i < 2; ++i) {
            const int rl = r0 + sub*64 + wm*32 + i*16 + g;
            #pragma unroll
            for (int j = 0; j < 4; ++j) {
                const int c = wn*32 + j*8 + t*2;
                const float b0 = sB[c], b1 = sB[c+1];
                float v0 = acc[i][j][0]+b0, v1 = acc[i][j][1]+b1;
                float v2 = acc[i][j][2]+b0, v3 = acc[i][j][3]+b1;
                if (EPI == 0) {
                    v0 = fmaxf(v0,0.f); v1 = fmaxf(v1,0.f);
                    v2 = fmaxf(v2,0.f); v3 = fmaxf(v3,0.f);
                }
                *(float2*)(Out + (size_t)rl*128 + c)     = make_float2(v0,v1);
                *(float2*)(Out + (size_t)(rl+8)*128 + c) = make_float2(v2,v3);
            }
        }
        __syncthreads();
    }
}

// ---------------- grid sync ----------------
__device__ __forceinline__ void gsync(unsigned* ctr, unsigned tgt) {
    __syncthreads();
    __threadfence();
    if (threadIdx.x == 0) {
        atomicAdd(ctr, 1u);
        while (*(volatile unsigned*)ctr < tgt) __nanosleep(32);
    }
    __syncthreads();
    __threadfence();
}
#define WG_BAR() asm volatile("bar.sync %0, 256;" :: "r"(1+wg) : "memory")

// ---------------- persistent dual-chain message-passing kernel (512 threads) ----------------
// Per level: gather(M) -> updGEMM -> {STG out, STS Y-frags} -> preGEMM -> STG M' -> gsync.
// Y never roundtrips through gmem for the pre-GEMM; out is write-only here.
#define CH_SMEM ((2*W_FRAG_SZ + 2*A_FRAG_SZ + 256) * 4)

__global__ __launch_bounds__(512, 1) void chain_kernel(
    float* __restrict__ out,
    const int* __restrict__ src,
    const float* __restrict__ f_pre_b, const float* __restrict__ f_upd_b,
    const float* __restrict__ b_pre_b, const float* __restrict__ b_upd_b)
{
    extern __shared__ unsigned sm[];
    unsigned* sWpre = sm;
    unsigned* sWupd = sm + W_FRAG_SZ;
    unsigned* sA0   = sm + 2*W_FRAG_SZ;
    unsigned* sA1   = sA0 + A_FRAG_SZ;
    float*    sB    = (float*)(sA1 + A_FRAG_SZ);   // [0,128) pre_b, [128,256) upd_b

    const int tid = threadIdx.x, lane = tid & 31, w = tid >> 5;
    const int wg = w >> 3;
    const int lt = tid & 255;
    const int wm = (w >> 2) & 1, wn = w & 3;
    const int g = lane >> 2, t = lane & 3;
    const bool fwd = blockIdx.x < CH;
    const int cc = fwd ? blockIdx.x : blockIdx.x - CH;
    const int r0 = cc * 128;
    const int cofs = fwd ? 0 : 128;
    unsigned* ctr = &g_bars[fwd ? 0 : 1];
    __half* Mbase = fwd ? g_Mf : g_Mb;
    const unsigned* wfpre = g_wf + (size_t)(fwd ? 0 : 2) * W_FRAG_SZ;
    const unsigned* wfupd = g_wf + (size_t)(fwd ? 1 : 3) * W_FRAG_SZ;
    const float* preB = fwd ? f_pre_b : b_pre_b;
    const float* updB = fwd ? f_upd_b : b_upd_b;
    unsigned* sAw = wg ? sA1 : sA0;

    // reverse CTAs build CSR col (scan done in ntgemm<1>); published by first gsync
    if (!fwd) {
        const int tot = LEVE*PKE;
        for (int e = cc*512 + tid; e < tot; e += CH*512) {
            const int lvl = e >> 16;
            const int le  = e & (PKE-1);
            const int pos = atomicAdd(&g_fill[lvl*PP + src[e]], 1);
            g_col[(size_t)lvl*PKE + pos] = le >> 3;
        }
    }

    for (int i = tid; i < W_FRAG_SZ/4; i += 512) {
        ((uint4*)sWpre)[i] = ((const uint4*)wfpre)[i];
        ((uint4*)sWupd)[i] = ((const uint4*)wfupd)[i];
    }
    if (tid < 32) {
        ((float4*)sB)[tid]       = ((const float4*)preB)[tid];
        ((float4*)(sB+128))[tid] = ((const float4*)updB)[tid];
    }
    __syncthreads();

    // ---- boundary level: Y = relu(upd_b) + h ; STG out + frag-stage into sAw ----
    {
        const int lvl0 = fwd ? 0 : LEVE;
        #pragma unroll
        for (int it = 0; it < 8; ++it) {
            const int idx = lt + 256*it;                // 64 rows x 32 c4 per wg
            const int r = idx >> 5, c4 = idx & 31;
            const size_t node = (size_t)lvl0*PP + r0 + wg*64 + r;
            const float4 ub = *(const float4*)(sB + 128 + c4*4);
            const float4 hv = *(const float4*)(g_h + node*128 + c4*4);
            float4 o;
            o.x = fmaxf(ub.x,0.f)+hv.x; o.y = fmaxf(ub.y,0.f)+hv.y;
            o.z = fmaxf(ub.z,0.f)+hv.z; o.w = fmaxf(ub.w,0.f)+hv.w;
            *(float4*)(out + node*256 + cofs + c4*4) = o;
            frag_storeA(sAw, r, c4, o);
        }
    }
    WG_BAR();

    unsigned tgt = 0;
    // ---- boundary pre-GEMM: M for first consumed level ----
    {
        const int l1 = fwd ? 1 : (LEVE-1);
        __half* Mnext = Mbase + (size_t)(l1 & 1)*PP*DD;
        float acc[2][4][4];
        gemm_core(sAw, sWpre, wm, wn, lane, acc);
        #pragma unroll
        for (int i = 0; i < 2; ++i) {
            const int rl = r0 + wg*64 + wm*32 + i*16 + g;
            #pragma unroll
            for (int j = 0; j < 4; ++j) {
                const int c = wn*32 + j*8 + t*2;
                const float b0 = sB[c], b1 = sB[c+1];
                *(__half2*)(Mnext + (size_t)rl*128 + c) =
                    __floats2half2_rn(fmaxf(acc[i][j][0]+b0,0.f), fmaxf(acc[i][j][1]+b1,0.f));
                *(__half2*)(Mnext + (size_t)(rl+8)*128 + c) =
                    __floats2half2_rn(fmaxf(acc[i][j][2]+b0,0.f), fmaxf(acc[i][j][3]+b1,0.f));
            }
        }
        tgt += CH;
        gsync(ctr, tgt);
    }

    for (int s = 0; s < LEVE; ++s) {
        const int l = fwd ? (1+s) : (LEVE-1-s);
        __half* Mbuf = Mbase + (size_t)(l & 1)*PP*DD;

        // ---- gather-mean of M into sAw ----
        #pragma unroll 1
        for (int it = 0; it < 8; ++it) {
            const int idx = lt + 256*it;
            const int r = idx >> 5, c4 = idx & 31;
            const int pl = r0 + wg*64 + r;
            float4 v = make_float4(0.f,0.f,0.f,0.f);
            if (fwd) {
                const int* sp = src + (size_t)(l-1)*PKE + pl*KK;
                #pragma unroll
                for (int k = 0; k < KK; ++k) {
                    const uint2 u = *(const uint2*)(Mbuf + (size_t)sp[k]*128 + c4*4);
                    const float2 f0 = __half22float2(*(const __half2*)&u.x);
                    const float2 f1 = __half22float2(*(const __half2*)&u.y);
                    v.x += f0.x; v.y += f0.y; v.z += f1.x; v.w += f1.y;
                }
                v.x *= 0.125f; v.y *= 0.125f; v.z *= 0.125f; v.w *= 0.125f;
            } else {
                const int* rpl = g_rp + l*(PP+1);
                const int b0 = rpl[pl], e0 = rpl[pl+1];
                const int* colsl = g_col + (size_t)l*PKE;
                for (int jj = b0; jj < e0; ++jj) {
                    const uint2 u = *(const uint2*)(Mbuf + (size_t)colsl[jj]*128 + c4*4);
                    const float2 f0 = __half22float2(*(const __half2*)&u.x);
                    const float2 f1 = __half22float2(*(const __half2*)&u.y);
                    v.x += f0.x; v.y += f0.y; v.z += f1.x; v.w += f1.y;
                }
                if (e0 > b0) {
                    const float inv = 1.0f/(float)(e0-b0);
                    v.x *= inv; v.y *= inv; v.z *= inv; v.w *= inv;
                }
            }
            frag_storeA(sAw, r, c4, v);
        }
        WG_BAR();

        // ---- update GEMM ----
        float acc[2][4][4];
        gemm_core(sAw, sWupd, wm, wn, lane, acc);
        WG_BAR();       // everyone done reading sAw before Y-frag overwrite

        // ---- epilogue: Y = relu(acc+updB)+h ; STG out ; STS Y-frags ----
        #pragma unroll
        for (int i = 0; i < 2; ++i) {
            const int rloc = wm*32 + i*16 + g;          // [0,64)
            const int rl = r0 + wg*64 + rloc;
            #pragma unroll
            for (int j = 0; j < 4; ++j) {
                const int c = wn*32 + j*8 + t*2;
                const float b0 = sB[128+c], b1 = sB[128+c+1];
                float v0 = fmaxf(acc[i][j][0]+b0, 0.f);
                float v1 = fmaxf(acc[i][j][1]+b1, 0.f);
                float v2 = fmaxf(acc[i][j][2]+b0, 0.f);
                float v3 = fmaxf(acc[i][j][3]+b1, 0.f);
                const size_t nlo = (size_t)l*PP + rl, nhi = nlo + 8;
                const float2 hlo = *(const float2*)(g_h + nlo*128 + c);
                const float2 hhi = *(const float2*)(g_h + nhi*128 + c);
                v0 += hlo.x; v1 += hlo.y; v2 += hhi.x; v3 += hhi.y;
                *(float2*)(out + nlo*256 + cofs + c) = make_float2(v0,v1);
                *(float2*)(out + nhi*256 + cofs + c) = make_float2(v2,v3);
                frag_store1(sAw, rloc,   c,   v0);
                frag_store1(sAw, rloc,   c+1, v1);
                frag_store1(sAw, rloc+8, c,   v2);
                frag_store1(sAw, rloc+8, c+1, v3);
            }
        }

        if (s < LEVE-1) {
            WG_BAR();
            // ---- pre GEMM: M for next level ----
            const int lnext = fwd ? (l+1) : (l-1);
            __half* Mnext = Mbase + (size_t)(lnext & 1)*PP*DD;
            float acc2[2][4][4];
            gemm_core(sAw, sWpre, wm, wn, lane, acc2);
            #pragma unroll
            for (int i = 0; i < 2; ++i) {
                const int rl = r0 + wg*64 + wm*32 + i*16 + g;
                #pragma unroll
                for (int j = 0; j < 4; ++j) {
                    const int c = wn*32 + j*8 + t*2;
                    const float b0 = sB[c], b1 = sB[c+1];
                    *(__half2*)(Mnext + (size_t)rl*128 + c) =
                        __floats2half2_rn(fmaxf(acc2[i][j][0]+b0,0.f), fmaxf(acc2[i][j][1]+b1,0.f));
                    *(__half2*)(Mnext + (size_t)(rl+8)*128 + c) =
                        __floats2half2_rn(fmaxf(acc2[i][j][2]+b0,0.f), fmaxf(acc2[i][j][3]+b1,0.f));
                }
            }
            tgt += CH;
            gsync(ctr, tgt);
        }
    }
}

// ---------------- launch ----------------
extern "C" void kernel_launch(void* const* d_in, const int* in_sizes, int n_in,
                              void* d_out, int out_size) {
    const float* x       = (const float*)d_in[0];
    const int*   src     = (const int*)  d_in[1];
    const float* nt_w1   = (const float*)d_in[2];
    const float* nt_b1   = (const float*)d_in[3];
    const float* nt_w2   = (const float*)d_in[4];
    const float* nt_b2   = (const float*)d_in[5];
    const float* f_pre_w = (const float*)d_in[6];
    const float* f_pre_b = (const float*)d_in[7];
    const float* f_upd_w = (const float*)d_in[8];
    const float* f_upd_b = (const float*)d_in[9];
    const float* b_pre_w = (const float*)d_in[10];
    const float* b_pre_b = (const float*)d_in[11];
    const float* b_upd_w = (const float*)d_in[12];
    const float* b_upd_b = (const float*)d_in[13];
    float* out = (float*)d_out;

    void *p_h, *p_hid, *p_wf;
    cudaGetSymbolAddress(&p_h,   g_h);
    cudaGetSymbolAddress(&p_hid, g_hid);
    cudaGetSymbolAddress(&p_wf,  g_wf);

    cudaFuncSetAttribute(ntgemm<0,1>,  cudaFuncAttributeMaxDynamicSharedMemorySize, NT_SMEM);
    cudaFuncSetAttribute(ntgemm<1,2>,  cudaFuncAttributeMaxDynamicSharedMemorySize, NT_SMEM);
    cudaFuncSetAttribute(chain_kernel, cudaFuncAttributeMaxDynamicSharedMemorySize, CH_SMEM);

    float* h   = (float*)p_h;
    float* hid = (float*)p_hid;
    unsigned* wf = (unsigned*)p_wf;

    build_wfrag<<<6, 256>>>(f_pre_w, f_upd_w, b_pre_w, b_upd_w, nt_w1, nt_w2);
    ntgemm<0,1><<<NTB + 64, 256, NT_SMEM>>>(x,   wf + (size_t)4*W_FRAG_SZ, nt_b1, hid, src);
    ntgemm<1,2><<<NTB + LEVE, 256, NT_SMEM>>>(hid, wf + (size_t)5*W_FRAG_SZ, nt_b2, h, src);
    chain_kernel<<<2*CH, 512, CH_SMEM>>>(out, src,
        f_pre_b, f_upd_b, b_pre_b, b_upd_b);
}

// round 8
// speedup vs baseline: 1.1296x; 1.1296x over previous
#include <cuda_runtime.h>
#include <cuda_fp16.h>
#include <cstdint>

#define NN 131072
#define DD 128
#define LL 16
#define PP 8192
#define KK 8
#define PKE (PP*KK)
#define LEVE (LL-1)
#define CH 64            // CTAs per chain
#define NTB2 (NN/128)    // 1024 fused-NT gemm blocks

// ---------------- scratch (static device globals; no allocation) ----------------
__device__ float  g_h[(size_t)NN*DD];
__device__ __half g_Mf[2*PP*DD];
__device__ __half g_Mb[2*PP*DD];
__device__ int    g_cnt[LEVE*PP];
__device__ int    g_rp[LEVE*(PP+1)];
__device__ int    g_fill[LEVE*PP];
__device__ int    g_col[LEVE*PKE];
__device__ unsigned g_bars[64];      // slot 0: fwd, slot 32: rev (separate lines)

#define A_FRAG_SZ (4*16*132)          // 8448 words
#define W_FRAG_SZ (16*16*66)          // 16896 words
__device__ unsigned g_wf[6*W_FRAG_SZ];   // 0 f_pre, 1 f_upd, 2 b_pre, 3 b_upd, 4 nt_w1, 5 nt_w2

// ---------------- tf32 / mma helpers ----------------
__device__ __forceinline__ unsigned tf32c(float f) {
    unsigned r;
    asm("cvt.rna.tf32.f32 %0, %1;" : "=r"(r) : "f"(f));
    return r;
}
__device__ __forceinline__ void mma8(float* d, const unsigned* a, const unsigned* b) {
    asm("mma.sync.aligned.m16n8k8.row.col.f32.tf32.tf32.f32 "
        "{%0,%1,%2,%3},{%4,%5,%6,%7},{%8,%9},{%0,%1,%2,%3};"
        : "+f"(d[0]), "+f"(d[1]), "+f"(d[2]), "+f"(d[3])
        : "r"(a[0]), "r"(a[1]), "r"(a[2]), "r"(a[3]), "r"(b[0]), "r"(b[1]));
}

__device__ __forceinline__ void frag_storeA(unsigned* sA, int r, int c4, float4 v) {
    unsigned* p = sA + (((r>>4)*16 + (c4>>1))*132) + ((r&7)*16) + ((c4&1)*2) + ((r&15)>>3);
    p[0] = tf32c(v.x); p[4] = tf32c(v.y); p[8] = tf32c(v.z); p[12] = tf32c(v.w);
}
__device__ __forceinline__ void frag_store1(unsigned* sA, int r, int k, float v) {
    sA[(((r>>4)*16 + (k>>3))*132) + ((r&7)*16) + ((k&3)*4) + (((k>>2)&1)*2) + ((r&15)>>3)] = tf32c(v);
}

// ---------------- prep: W fragments + CSR count + barrier zero ----------------
__global__ void prep_kernel(const float* w0, const float* w1, const float* w2,
                            const float* w3, const float* w4, const float* w5,
                            const int* __restrict__ src) {
    const int tid = threadIdx.x;
    if (blockIdx.x < 6) {
        const float* W;
        switch (blockIdx.x) {
            case 0: W = w0; break; case 1: W = w1; break; case 2: W = w2; break;
            case 3: W = w3; break; case 4: W = w4; break; default: W = w5; break;
        }
        unsigned* dst = g_wf + (size_t)blockIdx.x * W_FRAG_SZ;
        #pragma unroll
        for (int it = 0; it < 16; ++it) {
            const int idx = tid + 256*it;
            const int k = idx >> 5, c4 = idx & 31;
            const float4 v = ((const float4*)W)[idx];
            unsigned* p = dst + (((c4>>1)*16 + (k>>3))*66) + ((c4&1)*32) + ((k&3)*2) + ((k>>2)&1);
            p[0] = tf32c(v.x); p[8] = tf32c(v.y); p[16] = tf32c(v.z); p[24] = tf32c(v.w);
        }
        if (blockIdx.x == 0 && tid < 64) g_bars[tid] = 0;
    } else {
        const int b = blockIdx.x - 6;        // 122 count blocks
        const int tot = LEVE*PKE;
        for (int e = b*256 + tid; e < tot; e += 122*256)
            atomicAdd(&g_cnt[(e >> 16)*PP + src[e]], 1);
    }
}

// ---------------- GEMM core: 64x128 tile, 8 warps (wm in [0,2), wn in [0,4)) ----------------
__device__ __forceinline__ void gemm_core(const unsigned* __restrict__ sA,
                                          const unsigned* __restrict__ sW,
                                          int wm, int wn, int lane,
                                          float acc[2][4][4]) {
    #pragma unroll
    for (int i = 0; i < 2; ++i)
        #pragma unroll
        for (int j = 0; j < 4; ++j)
            #pragma unroll
            for (int q = 0; q < 4; ++q) acc[i][j][q] = 0.f;
    #pragma unroll
    for (int kb = 0; kb < 16; ++kb) {
        unsigned a[2][4];
        #pragma unroll
        for (int i = 0; i < 2; ++i) {
            const uint4 v = *(const uint4*)(sA + (((wm*2+i)*16 + kb)*132) + lane*4);
            a[i][0] = v.x; a[i][1] = v.y; a[i][2] = v.z; a[i][3] = v.w;
        }
        unsigned b[4][2];
        #pragma unroll
        for (int j = 0; j < 4; ++j) {
            const uint2 v = *(const uint2*)(sW + (((wn*4+j)*16 + kb)*66) + lane*2);
            b[j][0] = v.x; b[j][1] = v.y;
        }
        #pragma unroll
        for (int i = 0; i < 2; ++i)
            #pragma unroll
            for (int j = 0; j < 4; ++j)
                mma8(acc[i][j], a[i], b[j]);
    }
}

#define WG_BAR() asm volatile("bar.sync %0, 256;" :: "r"(1+wg) : "memory")

// ---------------- fused node transform (x -> relu(x@W1+b1)@W2+b2) + CSR scan ----------------
#define NTF_SMEM ((2*W_FRAG_SZ + 2*A_FRAG_SZ + 256) * 4)

__global__ __launch_bounds__(512, 1) void nt_fused(
    const float* __restrict__ x,
    const float* __restrict__ b1v, const float* __restrict__ b2v,
    float* __restrict__ Out)
{
    extern __shared__ unsigned sm[];
    const int tid = threadIdx.x;

    if (blockIdx.x >= NTB2) {            // 15 CSR scan blocks (512 threads)
        const int lvl = blockIdx.x - NTB2;
        const int base = lvl*PP;
        int c[16]; int sum = 0;
        #pragma unroll
        for (int j = 0; j < 16; ++j) { c[j] = g_cnt[base + tid*16 + j]; sum += c[j]; }
        int* sh = (int*)sm;
        sh[tid] = sum; __syncthreads();
        for (int d = 1; d < 512; d <<= 1) {
            int v = (tid >= d) ? sh[tid-d] : 0;
            __syncthreads();
            sh[tid] += v;
            __syncthreads();
        }
        int off = sh[tid] - sum;
        int* rpl = g_rp + lvl*(PP+1);
        #pragma unroll
        for (int j = 0; j < 16; ++j) {
            const int idx = tid*16 + j;
            rpl[idx] = off; g_fill[base + idx] = off; off += c[j];
        }
        if (tid == 511) rpl[PP] = off;
        return;
    }

    unsigned* sW1 = sm;
    unsigned* sW2 = sm + W_FRAG_SZ;
    unsigned* sA0 = sm + 2*W_FRAG_SZ;
    unsigned* sA1 = sA0 + A_FRAG_SZ;
    float*    sB  = (float*)(sA1 + A_FRAG_SZ);
    const int lane = tid & 31, w = tid >> 5;
    const int wg = w >> 3, lt = tid & 255;
    const int wm = (w >> 2) & 1, wn = w & 3;
    const int g = lane >> 2, t = lane & 3;
    const int r0 = blockIdx.x * 128;
    unsigned* sAw = wg ? sA1 : sA0;

    for (int i = tid; i < W_FRAG_SZ/4; i += 512) {
        ((uint4*)sW1)[i] = ((const uint4*)(g_wf + (size_t)4*W_FRAG_SZ))[i];
        ((uint4*)sW2)[i] = ((const uint4*)(g_wf + (size_t)5*W_FRAG_SZ))[i];
    }
    if (tid < 32) {
        ((float4*)sB)[tid]       = ((const float4*)b1v)[tid];
        ((float4*)(sB+128))[tid] = ((const float4*)b2v)[tid];
    }
    __syncthreads();

    // stage x tile
    #pragma unroll
    for (int it = 0; it < 8; ++it) {
        const int idx = lt + 256*it;
        const int r = idx >> 5, c4 = idx & 31;
        frag_storeA(sAw, r, c4,
            *(const float4*)(x + (size_t)(r0 + wg*64 + r)*128 + c4*4));
    }
    WG_BAR();
    float acc[2][4][4];
    gemm_core(sAw, sW1, wm, wn, lane, acc);
    WG_BAR();
    // relu(acc+b1) back into frags
    #pragma unroll
    for (int i = 0; i < 2; ++i) {
        const int rloc = wm*32 + i*16 + g;
        #pragma unroll
        for (int j = 0; j < 4; ++j) {
            const int c = wn*32 + j*8 + t*2;
            const float b0 = sB[c], b1 = sB[c+1];
            frag_store1(sAw, rloc,   c,   fmaxf(acc[i][j][0]+b0, 0.f));
            frag_store1(sAw, rloc,   c+1, fmaxf(acc[i][j][1]+b1, 0.f));
            frag_store1(sAw, rloc+8, c,   fmaxf(acc[i][j][2]+b0, 0.f));
            frag_store1(sAw, rloc+8, c+1, fmaxf(acc[i][j][3]+b1, 0.f));
        }
    }
    WG_BAR();
    float acc2[2][4][4];
    gemm_core(sAw, sW2, wm, wn, lane, acc2);
    #pragma unroll
    for (int i = 0; i < 2; ++i) {
        const int rl = r0 + wg*64 + wm*32 + i*16 + g;
        #pragma unroll
        for (int j = 0; j < 4; ++j) {
            const int c = wn*32 + j*8 + t*2;
            const float b0 = sB[128+c], b1 = sB[128+c+1];
            *(float2*)(Out + (size_t)rl*128 + c)
                = make_float2(acc2[i][j][0]+b0, acc2[i][j][1]+b1);
            *(float2*)(Out + (size_t)(rl+8)*128 + c)
                = make_float2(acc2[i][j][2]+b0, acc2[i][j][3]+b1);
        }
    }
}

// ---------------- split grid sync (CG pattern) ----------------
__device__ __forceinline__ void g_arrive(unsigned* ctr) {
    __syncthreads();
    __threadfence();                     // release: publish M
    if (threadIdx.x == 0) atomicAdd(ctr, 1u);
}
__device__ __forceinline__ void g_wait(unsigned* ctr, unsigned tgt) {
    if (threadIdx.x == 0) {
        unsigned v;
        do {
            asm volatile("ld.acquire.gpu.global.u32 %0, [%1];" : "=r"(v) : "l"(ctr) : "memory");
        } while (v < tgt);
    }
    __syncthreads();
}

// ---------------- persistent dual-chain message-passing kernel ----------------
#define CH_SMEM ((2*W_FRAG_SZ + 2*A_FRAG_SZ + 256) * 4)

__global__ __launch_bounds__(512, 1) void chain_kernel(
    float* __restrict__ out,
    const int* __restrict__ src,
    const float* __restrict__ f_pre_b, const float* __restrict__ f_upd_b,
    const float* __restrict__ b_pre_b, const float* __restrict__ b_upd_b)
{
    extern __shared__ unsigned sm[];
    unsigned* sWpre = sm;
    unsigned* sWupd = sm + W_FRAG_SZ;
    unsigned* sA0   = sm + 2*W_FRAG_SZ;
    unsigned* sA1   = sA0 + A_FRAG_SZ;
    float*    sB    = (float*)(sA1 + A_FRAG_SZ);

    const int tid = threadIdx.x, lane = tid & 31, w = tid >> 5;
    const int wg = w >> 3, lt = tid & 255;
    const int wm = (w >> 2) & 1, wn = w & 3;
    const int g = lane >> 2, t = lane & 3;
    const bool fwd = blockIdx.x < CH;
    const int cc = fwd ? blockIdx.x : blockIdx.x - CH;
    const int r0 = cc * 128;
    const int cofs = fwd ? 0 : 128;
    unsigned* ctr = &g_bars[fwd ? 0 : 32];
    __half* Mbase = fwd ? g_Mf : g_Mb;
    const unsigned* wfpre = g_wf + (size_t)(fwd ? 0 : 2) * W_FRAG_SZ;
    const unsigned* wfupd = g_wf + (size_t)(fwd ? 1 : 3) * W_FRAG_SZ;
    const float* preB = fwd ? f_pre_b : b_pre_b;
    const float* updB = fwd ? f_upd_b : b_upd_b;
    unsigned* sAw = wg ? sA1 : sA0;

    // reverse CTAs build CSR col (scan done in nt_fused); published by first g_arrive
    if (!fwd) {
        const int tot = LEVE*PKE;
        for (int e = cc*512 + tid; e < tot; e += CH*512) {
            const int lvl = e >> 16;
            const int le  = e & (PKE-1);
            const int pos = atomicAdd(&g_fill[lvl*PP + src[e]], 1);
            g_col[(size_t)lvl*PKE + pos] = le >> 3;
        }
    }

    for (int i = tid; i < W_FRAG_SZ/4; i += 512) {
        ((uint4*)sWpre)[i] = ((const uint4*)wfpre)[i];
        ((uint4*)sWupd)[i] = ((const uint4*)wfupd)[i];
    }
    if (tid < 32) {
        ((float4*)sB)[tid]       = ((const float4*)preB)[tid];
        ((float4*)(sB+128))[tid] = ((const float4*)updB)[tid];
    }
    __syncthreads();

    unsigned tgt = 0;
    // ---- boundary: Y0 = relu(updB)+h; frags + hold in regs; preGEMM; arrive; out; wait ----
    {
        const int lvl0 = fwd ? 0 : LEVE;
        float4 y0[8];
        #pragma unroll
        for (int it = 0; it < 8; ++it) {
            const int idx = lt + 256*it;
            const int r = idx >> 5, c4 = idx & 31;
            const size_t node = (size_t)lvl0*PP + r0 + wg*64 + r;
            const float4 ub = *(const float4*)(sB + 128 + c4*4);
            const float4 hv = *(const float4*)(g_h + node*128 + c4*4);
            float4 o;
            o.x = fmaxf(ub.x,0.f)+hv.x; o.y = fmaxf(ub.y,0.f)+hv.y;
            o.z = fmaxf(ub.z,0.f)+hv.z; o.w = fmaxf(ub.w,0.f)+hv.w;
            y0[it] = o;
            frag_storeA(sAw, r, c4, o);
        }
        WG_BAR();
        const int l1 = fwd ? 1 : (LEVE-1);
        __half* Mnext = Mbase + (size_t)(l1 & 1)*PP*DD;
        float acc[2][4][4];
        gemm_core(sAw, sWpre, wm, wn, lane, acc);
        #pragma unroll
        for (int i = 0; i < 2; ++i) {
            const int rl = r0 + wg*64 + wm*32 + i*16 + g;
            #pragma unroll
            for (int j = 0; j < 4; ++j) {
                const int c = wn*32 + j*8 + t*2;
                const float b0 = sB[c], b1 = sB[c+1];
                *(__half2*)(Mnext + (size_t)rl*128 + c) =
                    __floats2half2_rn(fmaxf(acc[i][j][0]+b0,0.f), fmaxf(acc[i][j][1]+b1,0.f));
                *(__half2*)(Mnext + (size_t)(rl+8)*128 + c) =
                    __floats2half2_rn(fmaxf(acc[i][j][2]+b0,0.f), fmaxf(acc[i][j][3]+b1,0.f));
            }
        }
        tgt += CH;
        g_arrive(ctr);
        #pragma unroll
        for (int it = 0; it < 8; ++it) {
            const int idx = lt + 256*it;
            const int r = idx >> 5, c4 = idx & 31;
            const size_t node = (size_t)lvl0*PP + r0 + wg*64 + r;
            *(float4*)(out + node*256 + cofs + c4*4) = y0[it];
        }
        g_wait(ctr, tgt);
    }

    for (int s = 0; s < LEVE; ++s) {
        const int l = fwd ? (1+s) : (LEVE-1-s);
        const bool last = (s == LEVE-1);
        __half* Mbuf = Mbase + (size_t)(l & 1)*PP*DD;

        // ---- gather-mean of M into sAw ----
        if (fwd) {
            #pragma unroll 2
            for (int it = 0; it < 8; ++it) {
                const int idx = lt + 256*it;
                const int r = idx >> 5, c4 = idx & 31;
                const int pl = r0 + wg*64 + r;
                const int* sp = src + (size_t)(l-1)*PKE + pl*KK;
                float4 v = make_float4(0.f,0.f,0.f,0.f);
                #pragma unroll
                for (int k = 0; k < KK; ++k) {
                    const uint2 u = *(const uint2*)(Mbuf + (size_t)sp[k]*128 + c4*4);
                    const float2 f0 = __half22float2(*(const __half2*)&u.x);
                    const float2 f1 = __half22float2(*(const __half2*)&u.y);
                    v.x += f0.x; v.y += f0.y; v.z += f1.x; v.w += f1.y;
                }
                v.x *= 0.125f; v.y *= 0.125f; v.z *= 0.125f; v.w *= 0.125f;
                frag_storeA(sAw, r, c4, v);
            }
        } else {
            #pragma unroll 1
            for (int it = 0; it < 8; ++it) {
                const int idx = lt + 256*it;
                const int r = idx >> 5, c4 = idx & 31;
                const int pl = r0 + wg*64 + r;
                const int* rpl = g_rp + l*(PP+1);
                const int b0 = rpl[pl], e0 = rpl[pl+1];
                const int* colsl = g_col + (size_t)l*PKE;
                float4 v = make_float4(0.f,0.f,0.f,0.f);
                int jj = b0;
                for (; jj + 4 <= e0; jj += 4) {          // 4-way MLP pipeline
                    const int d0 = colsl[jj], d1 = colsl[jj+1], d2 = colsl[jj+2], d3 = colsl[jj+3];
                    const uint2 u0 = *(const uint2*)(Mbuf + (size_t)d0*128 + c4*4);
                    const uint2 u1 = *(const uint2*)(Mbuf + (size_t)d1*128 + c4*4);
                    const uint2 u2 = *(const uint2*)(Mbuf + (size_t)d2*128 + c4*4);
                    const uint2 u3 = *(const uint2*)(Mbuf + (size_t)d3*128 + c4*4);
                    float2 a0 = __half22float2(*(const __half2*)&u0.x), b0_ = __half22float2(*(const __half2*)&u0.y);
                    float2 a1 = __half22float2(*(const __half2*)&u1.x), b1_ = __half22float2(*(const __half2*)&u1.y);
                    float2 a2 = __half22float2(*(const __half2*)&u2.x), b2_ = __half22float2(*(const __half2*)&u2.y);
                    float2 a3 = __half22float2(*(const __half2*)&u3.x), b3_ = __half22float2(*(const __half2*)&u3.y);
                    v.x += (a0.x+a1.x)+(a2.x+a3.x); v.y += (a0.y+a1.y)+(a2.y+a3.y);
                    v.z += (b0_.x+b1_.x)+(b2_.x+b3_.x); v.w += (b0_.y+b1_.y)+(b2_.y+b3_.y);
                }
                for (; jj < e0; ++jj) {
                    const uint2 u = *(const uint2*)(Mbuf + (size_t)colsl[jj]*128 + c4*4);
                    const float2 f0 = __half22float2(*(const __half2*)&u.x);
                    const float2 f1 = __half22float2(*(const __half2*)&u.y);
                    v.x += f0.x; v.y += f0.y; v.z += f1.x; v.w += f1.y;
                }
                if (e0 > b0) {
                    const float inv = 1.0f/(float)(e0-b0);
                    v.x *= inv; v.y *= inv; v.z *= inv; v.w *= inv;
                }
                frag_storeA(sAw, r, c4, v);
            }
        }
        WG_BAR();

        // ---- update GEMM ----
        float acc[2][4][4];
        gemm_core(sAw, sWupd, wm, wn, lane, acc);
        WG_BAR();

        // ---- epilogue: Y = relu(acc+updB)+h; keep Y in acc; frags for preGEMM ----
        #pragma unroll
        for (int i = 0; i < 2; ++i) {
            const int rloc = wm*32 + i*16 + g;
            const int rl = r0 + wg*64 + rloc;
            #pragma unroll
            for (int j = 0; j < 4; ++j) {
                const int c = wn*32 + j*8 + t*2;
                const float b0 = sB[128+c], b1 = sB[128+c+1];
                float v0 = fmaxf(acc[i][j][0]+b0, 0.f);
                float v1 = fmaxf(acc[i][j][1]+b1, 0.f);
                float v2 = fmaxf(acc[i][j][2]+b0, 0.f);
                float v3 = fmaxf(acc[i][j][3]+b1, 0.f);
                const size_t nlo = (size_t)l*PP + rl, nhi = nlo + 8;
                const float2 hlo = *(const float2*)(g_h + nlo*128 + c);
                const float2 hhi = *(const float2*)(g_h + nhi*128 + c);
                v0 += hlo.x; v1 += hlo.y; v2 += hhi.x; v3 += hhi.y;
                if (!last) {
                    frag_store1(sAw, rloc,   c,   v0);
                    frag_store1(sAw, rloc,   c+1, v1);
                    frag_store1(sAw, rloc+8, c,   v2);
                    frag_store1(sAw, rloc+8, c+1, v3);
                }
                acc[i][j][0] = v0; acc[i][j][1] = v1;
                acc[i][j][2] = v2; acc[i][j][3] = v3;
            }
        }

        if (!last) {
            WG_BAR();
            // ---- pre GEMM: M for next level; publish; overlap out-write with wait ----
            const int lnext = fwd ? (l+1) : (l-1);
            __half* Mnext = Mbase + (size_t)(lnext & 1)*PP*DD;
            float acc2[2][4][4];
            gemm_core(sAw, sWpre, wm, wn, lane, acc2);
            #pragma unroll
            for (int i = 0; i < 2; ++i) {
                const int rl = r0 + wg*64 + wm*32 + i*16 + g;
                #pragma unroll
                for (int j = 0; j < 4; ++j) {
                    const int c = wn*32 + j*8 + t*2;
                    const float b0 = sB[c], b1 = sB[c+1];
                    *(__half2*)(Mnext + (size_t)rl*128 + c) =
                        __floats2half2_rn(fmaxf(acc2[i][j][0]+b0,0.f), fmaxf(acc2[i][j][1]+b1,0.f));
                    *(__half2*)(Mnext + (size_t)(rl+8)*128 + c) =
                        __floats2half2_rn(fmaxf(acc2[i][j][2]+b0,0.f), fmaxf(acc2[i][j][3]+b1,0.f));
                }
            }
            tgt += CH;
            g_arrive(ctr);
        }

        // ---- out-write from Y held in acc (off the publish path) ----
        #pragma unroll
        for (int i = 0; i < 2; ++i) {
            const int rl = r0 + wg*64 + wm*32 + i*16 + g;
            #pragma unroll
            for (int j = 0; j < 4; ++j) {
                const int c = wn*32 + j*8 + t*2;
                const size_t nlo = (size_t)l*PP + rl, nhi = nlo + 8;
                *(float2*)(out + nlo*256 + cofs + c) = make_float2(acc[i][j][0], acc[i][j][1]);
                *(float2*)(out + nhi*256 + cofs + c) = make_float2(acc[i][j][2], acc[i][j][3]);
            }
        }

        if (!last) g_wait(ctr, tgt);
    }
}

// ---------------- launch ----------------
extern "C" void kernel_launch(void* const* d_in, const int* in_sizes, int n_in,
                              void* d_out, int out_size) {
    const float* x       = (const float*)d_in[0];
    const int*   src     = (const int*)  d_in[1];
    const float* nt_w1   = (const float*)d_in[2];
    const float* nt_b1   = (const float*)d_in[3];
    const float* nt_w2   = (const float*)d_in[4];
    const float* nt_b2   = (const float*)d_in[5];
    const float* f_pre_w = (const float*)d_in[6];
    const float* f_pre_b = (const float*)d_in[7];
    const float* f_upd_w = (const float*)d_in[8];
    const float* f_upd_b = (const float*)d_in[9];
    const float* b_pre_w = (const float*)d_in[10];
    const float* b_pre_b = (const float*)d_in[11];
    const float* b_upd_w = (const float*)d_in[12];
    const float* b_upd_b = (const float*)d_in[13];
    float* out = (float*)d_out;

    void *p_h, *p_cnt;
    cudaGetSymbolAddress(&p_h,   g_h);
    cudaGetSymbolAddress(&p_cnt, g_cnt);

    cudaFuncSetAttribute(nt_fused,     cudaFuncAttributeMaxDynamicSharedMemorySize, NTF_SMEM);
    cudaFuncSetAttribute(chain_kernel, cudaFuncAttributeMaxDynamicSharedMemorySize, CH_SMEM);

    float* h = (float*)p_h;

    cudaMemsetAsync(p_cnt, 0, (size_t)LEVE*PP*sizeof(int));
    prep_kernel<<<128, 256>>>(f_pre_w, f_upd_w, b_pre_w, b_upd_w, nt_w1, nt_w2, src);
    nt_fused<<<NTB2 + LEVE, 512, NTF_SMEM>>>(x, nt_b1, nt_b2, h);
    chain_kernel<<<2*CH, 512, CH_SMEM>>>(out, src,
        f_pre_b, f_upd_b, b_pre_b, b_upd_b);
}

// round 9
// speedup vs baseline: 1.2521x; 1.1084x over previous
#include <cuda_runtime.h>
#include <cuda_fp16.h>
#include <cstdint>

#define NN 131072
#define DD 128
#define LL 16
#define PP 8192
#define KK 8
#define PKE (PP*KK)
#define LEVE (LL-1)
#define CH 64            // CTAs per chain
#define NTB2 (NN/128)    // 1024 fused-NT gemm blocks

// ---------------- scratch (static device globals; no allocation) ----------------
__device__ float  g_h[(size_t)NN*DD];
__device__ __half g_Mf[2*PP*DD];
__device__ __half g_Mb[2*PP*DD];
__device__ int    g_cnt[LEVE*PP];
__device__ int    g_rp[LEVE*(PP+1)];
__device__ int    g_fill[LEVE*PP];
__device__ int    g_col[LEVE*PKE];
__device__ unsigned g_bars[64];      // slot 0: fwd, slot 32: rev (separate lines)

#define A_FRAG_SZ (4*16*132)          // 8448 words
#define W_FRAG_SZ (16*16*66)          // 16896 words
__device__ unsigned g_wf[6*W_FRAG_SZ];   // 0 f_pre, 1 f_upd, 2 b_pre, 3 b_upd, 4 nt_w1, 5 nt_w2

// ---------------- tf32 / mma helpers ----------------
__device__ __forceinline__ unsigned tf32c(float f) {
    unsigned r;
    asm("cvt.rna.tf32.f32 %0, %1;" : "=r"(r) : "f"(f));
    return r;
}
__device__ __forceinline__ void mma8(float* d, const unsigned* a, const unsigned* b) {
    asm("mma.sync.aligned.m16n8k8.row.col.f32.tf32.tf32.f32 "
        "{%0,%1,%2,%3},{%4,%5,%6,%7},{%8,%9},{%0,%1,%2,%3};"
        : "+f"(d[0]), "+f"(d[1]), "+f"(d[2]), "+f"(d[3])
        : "r"(a[0]), "r"(a[1]), "r"(a[2]), "r"(a[3]), "r"(b[0]), "r"(b[1]));
}

__device__ __forceinline__ void frag_storeA(unsigned* sA, int r, int c4, float4 v) {
    unsigned* p = sA + (((r>>4)*16 + (c4>>1))*132) + ((r&7)*16) + ((c4&1)*2) + ((r&15)>>3);
    p[0] = tf32c(v.x); p[4] = tf32c(v.y); p[8] = tf32c(v.z); p[12] = tf32c(v.w);
}
__device__ __forceinline__ void frag_store1(unsigned* sA, int r, int k, float v) {
    sA[(((r>>4)*16 + (k>>3))*132) + ((r&7)*16) + ((k&3)*4) + (((k>>2)&1)*2) + ((r&15)>>3)] = tf32c(v);
}

// ---------------- prep: W fragments + CSR count + barrier zero ----------------
#define CNTB 290
__global__ void prep_kernel(const float* w0, const float* w1, const float* w2,
                            const float* w3, const float* w4, const float* w5,
                            const int* __restrict__ src) {
    const int tid = threadIdx.x;
    if (blockIdx.x < 6) {
        const float* W;
        switch (blockIdx.x) {
            case 0: W = w0; break; case 1: W = w1; break; case 2: W = w2; break;
            case 3: W = w3; break; case 4: W = w4; break; default: W = w5; break;
        }
        unsigned* dst = g_wf + (size_t)blockIdx.x * W_FRAG_SZ;
        #pragma unroll
        for (int it = 0; it < 16; ++it) {
            const int idx = tid + 256*it;
            const int k = idx >> 5, c4 = idx & 31;
            const float4 v = ((const float4*)W)[idx];
            unsigned* p = dst + (((c4>>1)*16 + (k>>3))*66) + ((c4&1)*32) + ((k&3)*2) + ((k>>2)&1);
            p[0] = tf32c(v.x); p[8] = tf32c(v.y); p[16] = tf32c(v.z); p[24] = tf32c(v.w);
        }
        if (blockIdx.x == 0 && tid < 64) g_bars[tid] = 0;
    } else {
        const int b = blockIdx.x - 6;        // CNTB count blocks
        const int tot = LEVE*PKE;
        for (int e = b*256 + tid; e < tot; e += CNTB*256)
            atomicAdd(&g_cnt[(e >> 16)*PP + src[e]], 1);
    }
}

// ---------------- GEMM core: 64x128 tile, 8 warps (wm in [0,2), wn in [0,4)) ----------------
__device__ __forceinline__ void gemm_core(const unsigned* __restrict__ sA,
                                          const unsigned* __restrict__ sW,
                                          int wm, int wn, int lane,
                                          float acc[2][4][4]) {
    #pragma unroll
    for (int i = 0; i < 2; ++i)
        #pragma unroll
        for (int j = 0; j < 4; ++j)
            #pragma unroll
            for (int q = 0; q < 4; ++q) acc[i][j][q] = 0.f;
    #pragma unroll
    for (int kb = 0; kb < 16; ++kb) {
        unsigned a[2][4];
        #pragma unroll
        for (int i = 0; i < 2; ++i) {
            const uint4 v = *(const uint4*)(sA + (((wm*2+i)*16 + kb)*132) + lane*4);
            a[i][0] = v.x; a[i][1] = v.y; a[i][2] = v.z; a[i][3] = v.w;
        }
        unsigned b[4][2];
        #pragma unroll
        for (int j = 0; j < 4; ++j) {
            const uint2 v = *(const uint2*)(sW + (((wn*4+j)*16 + kb)*66) + lane*2);
            b[j][0] = v.x; b[j][1] = v.y;
        }
        #pragma unroll
        for (int i = 0; i < 2; ++i)
            #pragma unroll
            for (int j = 0; j < 4; ++j)
                mma8(acc[i][j], a[i], b[j]);
    }
}

#define WG_BAR() asm volatile("bar.sync %0, 256;" :: "r"(1+wg) : "memory")

// ---------------- fused node transform + CSR scan ----------------
#define NTF_SMEM ((2*W_FRAG_SZ + 2*A_FRAG_SZ + 256) * 4)

__global__ __launch_bounds__(512, 1) void nt_fused(
    const float* __restrict__ x,
    const float* __restrict__ b1v, const float* __restrict__ b2v,
    float* __restrict__ Out)
{
    extern __shared__ unsigned sm[];
    const int tid = threadIdx.x;

    if (blockIdx.x >= NTB2) {            // 15 CSR scan blocks
        const int lvl = blockIdx.x - NTB2;
        const int base = lvl*PP;
        int c[16]; int sum = 0;
        #pragma unroll
        for (int j = 0; j < 16; ++j) { c[j] = g_cnt[base + tid*16 + j]; sum += c[j]; }
        int* sh = (int*)sm;
        sh[tid] = sum; __syncthreads();
        for (int d = 1; d < 512; d <<= 1) {
            int v = (tid >= d) ? sh[tid-d] : 0;
            __syncthreads();
            sh[tid] += v;
            __syncthreads();
        }
        int off = sh[tid] - sum;
        int* rpl = g_rp + lvl*(PP+1);
        #pragma unroll
        for (int j = 0; j < 16; ++j) {
            const int idx = tid*16 + j;
            rpl[idx] = off; g_fill[base + idx] = off; off += c[j];
        }
        if (tid == 511) rpl[PP] = off;
        return;
    }

    unsigned* sW1 = sm;
    unsigned* sW2 = sm + W_FRAG_SZ;
    unsigned* sA0 = sm + 2*W_FRAG_SZ;
    unsigned* sA1 = sA0 + A_FRAG_SZ;
    float*    sB  = (float*)(sA1 + A_FRAG_SZ);
    const int lane = tid & 31, w = tid >> 5;
    const int wg = w >> 3, lt = tid & 255;
    const int wm = (w >> 2) & 1, wn = w & 3;
    const int g = lane >> 2, t = lane & 3;
    const int r0 = blockIdx.x * 128;
    unsigned* sAw = wg ? sA1 : sA0;

    for (int i = tid; i < W_FRAG_SZ/4; i += 512) {
        ((uint4*)sW1)[i] = ((const uint4*)(g_wf + (size_t)4*W_FRAG_SZ))[i];
        ((uint4*)sW2)[i] = ((const uint4*)(g_wf + (size_t)5*W_FRAG_SZ))[i];
    }
    if (tid < 32) {
        ((float4*)sB)[tid]       = ((const float4*)b1v)[tid];
        ((float4*)(sB+128))[tid] = ((const float4*)b2v)[tid];
    }
    __syncthreads();

    #pragma unroll
    for (int it = 0; it < 8; ++it) {
        const int idx = lt + 256*it;
        const int r = idx >> 5, c4 = idx & 31;
        frag_storeA(sAw, r, c4,
            *(const float4*)(x + (size_t)(r0 + wg*64 + r)*128 + c4*4));
    }
    WG_BAR();
    float acc[2][4][4];
    gemm_core(sAw, sW1, wm, wn, lane, acc);
    WG_BAR();
    #pragma unroll
    for (int i = 0; i < 2; ++i) {
        const int rloc = wm*32 + i*16 + g;
        #pragma unroll
        for (int j = 0; j < 4; ++j) {
            const int c = wn*32 + j*8 + t*2;
            const float b0 = sB[c], b1 = sB[c+1];
            frag_store1(sAw, rloc,   c,   fmaxf(acc[i][j][0]+b0, 0.f));
            frag_store1(sAw, rloc,   c+1, fmaxf(acc[i][j][1]+b1, 0.f));
            frag_store1(sAw, rloc+8, c,   fmaxf(acc[i][j][2]+b0, 0.f));
            frag_store1(sAw, rloc+8, c+1, fmaxf(acc[i][j][3]+b1, 0.f));
        }
    }
    WG_BAR();
    float acc2[2][4][4];
    gemm_core(sAw, sW2, wm, wn, lane, acc2);
    #pragma unroll
    for (int i = 0; i < 2; ++i) {
        const int rl = r0 + wg*64 + wm*32 + i*16 + g;
        #pragma unroll
        for (int j = 0; j < 4; ++j) {
            const int c = wn*32 + j*8 + t*2;
            const float b0 = sB[128+c], b1 = sB[128+c+1];
            *(float2*)(Out + (size_t)rl*128 + c)
                = make_float2(acc2[i][j][0]+b0, acc2[i][j][1]+b1);
            *(float2*)(Out + (size_t)(rl+8)*128 + c)
                = make_float2(acc2[i][j][2]+b0, acc2[i][j][3]+b1);
        }
    }
}

// ---------------- split grid sync ----------------
__device__ __forceinline__ void g_arrive(unsigned* ctr) {
    __syncthreads();
    __threadfence();
    if (threadIdx.x == 0) atomicAdd(ctr, 1u);
}
__device__ __forceinline__ void g_wait(unsigned* ctr, unsigned tgt) {
    if (threadIdx.x == 0) {
        unsigned v;
        do {
            asm volatile("ld.acquire.gpu.global.u32 %0, [%1];" : "=r"(v) : "l"(ctr) : "memory");
        } while (v < tgt);
    }
    __syncthreads();
}

// ---------------- helpers: accumulate a uint4 of 8 fp16 into 8 floats ----------------
__device__ __forceinline__ void acc8(float* f, uint4 u) {
    const float2 a = __half22float2(*(const __half2*)&u.x);
    const float2 b = __half22float2(*(const __half2*)&u.y);
    const float2 c = __half22float2(*(const __half2*)&u.z);
    const float2 d = __half22float2(*(const __half2*)&u.w);
    f[0]+=a.x; f[1]+=a.y; f[2]+=b.x; f[3]+=b.y;
    f[4]+=c.x; f[5]+=c.y; f[6]+=d.x; f[7]+=d.y;
}

// ---------------- persistent dual-chain message-passing kernel ----------------
#define CH_SMEM ((2*W_FRAG_SZ + 2*A_FRAG_SZ + 256) * 4)

__global__ __launch_bounds__(512, 1) void chain_kernel(
    float* __restrict__ out,
    const int* __restrict__ src,
    const float* __restrict__ f_pre_b, const float* __restrict__ f_upd_b,
    const float* __restrict__ b_pre_b, const float* __restrict__ b_upd_b)
{
    extern __shared__ unsigned sm[];
    unsigned* sWpre = sm;
    unsigned* sWupd = sm + W_FRAG_SZ;
    unsigned* sA0   = sm + 2*W_FRAG_SZ;
    unsigned* sA1   = sA0 + A_FRAG_SZ;
    float*    sB    = (float*)(sA1 + A_FRAG_SZ);

    const int tid = threadIdx.x, lane = tid & 31, w = tid >> 5;
    const int wg = w >> 3, lt = tid & 255;
    const int wm = (w >> 2) & 1, wn = w & 3;
    const int g = lane >> 2, t = lane & 3;
    const bool fwd = blockIdx.x < CH;
    const int cc = fwd ? blockIdx.x : blockIdx.x - CH;
    const int r0 = cc * 128;
    const int cofs = fwd ? 0 : 128;
    unsigned* ctr = &g_bars[fwd ? 0 : 32];
    __half* Mbase = fwd ? g_Mf : g_Mb;
    const unsigned* wfpre = g_wf + (size_t)(fwd ? 0 : 2) * W_FRAG_SZ;
    const unsigned* wfupd = g_wf + (size_t)(fwd ? 1 : 3) * W_FRAG_SZ;
    const float* preB = fwd ? f_pre_b : b_pre_b;
    const float* updB = fwd ? f_upd_b : b_upd_b;
    unsigned* sAw = wg ? sA1 : sA0;

    if (!fwd) {
        const int tot = LEVE*PKE;
        for (int e = cc*512 + tid; e < tot; e += CH*512) {
            const int lvl = e >> 16;
            const int le  = e & (PKE-1);
            const int pos = atomicAdd(&g_fill[lvl*PP + src[e]], 1);
            g_col[(size_t)lvl*PKE + pos] = le >> 3;
        }
    }

    for (int i = tid; i < W_FRAG_SZ/4; i += 512) {
        ((uint4*)sWpre)[i] = ((const uint4*)wfpre)[i];
        ((uint4*)sWupd)[i] = ((const uint4*)wfupd)[i];
    }
    if (tid < 32) {
        ((float4*)sB)[tid]       = ((const float4*)preB)[tid];
        ((float4*)(sB+128))[tid] = ((const float4*)updB)[tid];
    }
    __syncthreads();

    unsigned tgt = 0;
    // ---- boundary level ----
    {
        const int lvl0 = fwd ? 0 : LEVE;
        float4 y0[8];
        #pragma unroll
        for (int it = 0; it < 8; ++it) {
            const int idx = lt + 256*it;
            const int r = idx >> 5, c4 = idx & 31;
            const size_t node = (size_t)lvl0*PP + r0 + wg*64 + r;
            const float4 ub = *(const float4*)(sB + 128 + c4*4);
            const float4 hv = *(const float4*)(g_h + node*128 + c4*4);
            float4 o;
            o.x = fmaxf(ub.x,0.f)+hv.x; o.y = fmaxf(ub.y,0.f)+hv.y;
            o.z = fmaxf(ub.z,0.f)+hv.z; o.w = fmaxf(ub.w,0.f)+hv.w;
            y0[it] = o;
            frag_storeA(sAw, r, c4, o);
        }
        WG_BAR();
        const int l1 = fwd ? 1 : (LEVE-1);
        __half* Mnext = Mbase + (size_t)(l1 & 1)*PP*DD;
        float acc[2][4][4];
        gemm_core(sAw, sWpre, wm, wn, lane, acc);
        #pragma unroll
        for (int i = 0; i < 2; ++i) {
            const int rl = r0 + wg*64 + wm*32 + i*16 + g;
            #pragma unroll
            for (int j = 0; j < 4; ++j) {
                const int c = wn*32 + j*8 + t*2;
                const float b0 = sB[c], b1 = sB[c+1];
                *(__half2*)(Mnext + (size_t)rl*128 + c) =
                    __floats2half2_rn(fmaxf(acc[i][j][0]+b0,0.f), fmaxf(acc[i][j][1]+b1,0.f));
                *(__half2*)(Mnext + (size_t)(rl+8)*128 + c) =
                    __floats2half2_rn(fmaxf(acc[i][j][2]+b0,0.f), fmaxf(acc[i][j][3]+b1,0.f));
            }
        }
        tgt += CH;
        g_arrive(ctr);
        #pragma unroll
        for (int it = 0; it < 8; ++it) {
            const int idx = lt + 256*it;
            const int r = idx >> 5, c4 = idx & 31;
            const size_t node = (size_t)lvl0*PP + r0 + wg*64 + r;
            *(float4*)(out + node*256 + cofs + c4*4) = y0[it];
        }
        g_wait(ctr, tgt);
    }

    for (int s = 0; s < LEVE; ++s) {
        const int l = fwd ? (1+s) : (LEVE-1-s);
        const bool last = (s == LEVE-1);
        __half* Mbuf = Mbase + (size_t)(l & 1)*PP*DD;

        // ---- gather-mean of M into sAw: thread = (row pair-of-16, c8 chunk) ----
        // idx = lt + 256*it ; r = idx>>4 in [0,64) ; c8 = idx&15 (8 fp16 cols = one uint4)
        #pragma unroll
        for (int it = 0; it < 4; ++it) {
            const int idx = lt + 256*it;
            const int r = idx >> 4, c8 = idx & 15;
            const int pl = r0 + wg*64 + r;
            float f[8];
            #pragma unroll
            for (int q = 0; q < 8; ++q) f[q] = 0.f;
            float inv = 0.125f;
            if (fwd) {
                const int4* sp = (const int4*)(src + (size_t)(l-1)*PKE + pl*KK);
                const int4 ia = sp[0], ib = sp[1];
                acc8(f, *(const uint4*)(Mbuf + (size_t)ia.x*128 + c8*8));
                acc8(f, *(const uint4*)(Mbuf + (size_t)ia.y*128 + c8*8));
                acc8(f, *(const uint4*)(Mbuf + (size_t)ia.z*128 + c8*8));
                acc8(f, *(const uint4*)(Mbuf + (size_t)ia.w*128 + c8*8));
                acc8(f, *(const uint4*)(Mbuf + (size_t)ib.x*128 + c8*8));
                acc8(f, *(const uint4*)(Mbuf + (size_t)ib.y*128 + c8*8));
                acc8(f, *(const uint4*)(Mbuf + (size_t)ib.z*128 + c8*8));
                acc8(f, *(const uint4*)(Mbuf + (size_t)ib.w*128 + c8*8));
            } else {
                const int* rpl = g_rp + l*(PP+1);
                const int b0 = rpl[pl], e0 = rpl[pl+1];
                const int* colsl = g_col + (size_t)l*PKE;
                int jj = b0;
                for (; jj + 2 <= e0; jj += 2) {
                    const int d0 = colsl[jj], d1 = colsl[jj+1];
                    const uint4 u0 = *(const uint4*)(Mbuf + (size_t)d0*128 + c8*8);
                    const uint4 u1 = *(const uint4*)(Mbuf + (size_t)d1*128 + c8*8);
                    acc8(f, u0); acc8(f, u1);
                }
                if (jj < e0)
                    acc8(f, *(const uint4*)(Mbuf + (size_t)colsl[jj]*128 + c8*8));
                inv = (e0 > b0) ? 1.0f/(float)(e0-b0) : 0.f;
            }
            #pragma unroll
            for (int q = 0; q < 8; ++q) f[q] *= inv;
            frag_storeA(sAw, r, 2*c8,   make_float4(f[0], f[1], f[2], f[3]));
            frag_storeA(sAw, r, 2*c8+1, make_float4(f[4], f[5], f[6], f[7]));
        }
        WG_BAR();

        // ---- update GEMM ----
        float acc[2][4][4];
        gemm_core(sAw, sWupd, wm, wn, lane, acc);
        WG_BAR();

        // ---- epilogue: Y = relu(acc+updB)+h; keep Y in acc; frags for preGEMM ----
        #pragma unroll
        for (int i = 0; i < 2; ++i) {
            const int rloc = wm*32 + i*16 + g;
            const int rl = r0 + wg*64 + rloc;
            #pragma unroll
            for (int j = 0; j < 4; ++j) {
                const int c = wn*32 + j*8 + t*2;
                const float b0 = sB[128+c], b1 = sB[128+c+1];
                float v0 = fmaxf(acc[i][j][0]+b0, 0.f);
                float v1 = fmaxf(acc[i][j][1]+b1, 0.f);
                float v2 = fmaxf(acc[i][j][2]+b0, 0.f);
                float v3 = fmaxf(acc[i][j][3]+b1, 0.f);
                const size_t nlo = (size_t)l*PP + rl, nhi = nlo + 8;
                const float2 hlo = *(const float2*)(g_h + nlo*128 + c);
                const float2 hhi = *(const float2*)(g_h + nhi*128 + c);
                v0 += hlo.x; v1 += hlo.y; v2 += hhi.x; v3 += hhi.y;
                if (!last) {
                    frag_store1(sAw, rloc,   c,   v0);
                    frag_store1(sAw, rloc,   c+1, v1);
                    frag_store1(sAw, rloc+8, c,   v2);
                    frag_store1(sAw, rloc+8, c+1, v3);
                }
                acc[i][j][0] = v0; acc[i][j][1] = v1;
                acc[i][j][2] = v2; acc[i][j][3] = v3;
            }
        }

        if (!last) {
            WG_BAR();
            const int lnext = fwd ? (l+1) : (l-1);
            __half* Mnext = Mbase + (size_t)(lnext & 1)*PP*DD;
            float acc2[2][4][4];
            gemm_core(sAw, sWpre, wm, wn, lane, acc2);
            #pragma unroll
            for (int i = 0; i < 2; ++i) {
                const int rl = r0 + wg*64 + wm*32 + i*16 + g;
                #pragma unroll
                for (int j = 0; j < 4; ++j) {
                    const int c = wn*32 + j*8 + t*2;
                    const float b0 = sB[c], b1 = sB[c+1];
                    *(__half2*)(Mnext + (size_t)rl*128 + c) =
                        __floats2half2_rn(fmaxf(acc2[i][j][0]+b0,0.f), fmaxf(acc2[i][j][1]+b1,0.f));
                    *(__half2*)(Mnext + (size_t)(rl+8)*128 + c) =
                        __floats2half2_rn(fmaxf(acc2[i][j][2]+b0,0.f), fmaxf(acc2[i][j][3]+b1,0.f));
                }
            }
            tgt += CH;
            g_arrive(ctr);
        }

        // ---- out-write from Y held in acc (off the publish path) ----
        #pragma unroll
        for (int i = 0; i < 2; ++i) {
            const int rl = r0 + wg*64 + wm*32 + i*16 + g;
            #pragma unroll
            for (int j = 0; j < 4; ++j) {
                const int c = wn*32 + j*8 + t*2;
                const size_t nlo = (size_t)l*PP + rl, nhi = nlo + 8;
                *(float2*)(out + nlo*256 + cofs + c) = make_float2(acc[i][j][0], acc[i][j][1]);
                *(float2*)(out + nhi*256 + cofs + c) = make_float2(acc[i][j][2], acc[i][j][3]);
            }
        }

        if (!last) g_wait(ctr, tgt);
    }
}

// ---------------- launch ----------------
extern "C" void kernel_launch(void* const* d_in, const int* in_sizes, int n_in,
                              void* d_out, int out_size) {
    const float* x       = (const float*)d_in[0];
    const int*   src     = (const int*)  d_in[1];
    const float* nt_w1   = (const float*)d_in[2];
    const float* nt_b1   = (const float*)d_in[3];
    const float* nt_w2   = (const float*)d_in[4];
    const float* nt_b2   = (const float*)d_in[5];
    const float* f_pre_w = (const float*)d_in[6];
    const float* f_pre_b = (const float*)d_in[7];
    const float* f_upd_w = (const float*)d_in[8];
    const float* f_upd_b = (const float*)d_in[9];
    const float* b_pre_w = (const float*)d_in[10];
    const float* b_pre_b = (const float*)d_in[11];
    const float* b_upd_w = (const float*)d_in[12];
    const float* b_upd_b = (const float*)d_in[13];
    float* out = (float*)d_out;

    void *p_h, *p_cnt;
    cudaGetSymbolAddress(&p_h,   g_h);
    cudaGetSymbolAddress(&p_cnt, g_cnt);

    cudaFuncSetAttribute(nt_fused,     cudaFuncAttributeMaxDynamicSharedMemorySize, NTF_SMEM);
    cudaFuncSetAttribute(chain_kernel, cudaFuncAttributeMaxDynamicSharedMemorySize, CH_SMEM);

    float* h = (float*)p_h;

    cudaMemsetAsync(p_cnt, 0, (size_t)LEVE*PP*sizeof(int));
    prep_kernel<<<6 + CNTB, 256>>>(f_pre_w, f_upd_w, b_pre_w, b_upd_w, nt_w1, nt_w2, src);
    nt_fused<<<NTB2 + LEVE, 512, NTF_SMEM>>>(x, nt_b1, nt_b2, h);
    chain_kernel<<<2*CH, 512, CH_SMEM>>>(out, src,
        f_pre_b, f_upd_b, b_pre_b, b_upd_b);
}

// round 10
// speedup vs baseline: 1.5426x; 1.2321x over previous
#include <cuda_runtime.h>
#include <cuda_fp16.h>
#include <cstdint>

#define NN 131072
#define DD 128
#define LL 16
#define PP 8192
#define KK 8
#define PKE (PP*KK)
#define LEVE (LL-1)
#define CH 64            // CTAs per chain
#define NTB3 (NN/64)     // 2048 NT gemm blocks (64 rows each)

// ---------------- scratch ----------------
__device__ float  g_h[(size_t)NN*DD];
__device__ __half g_Mf[2*PP*DD];
__device__ __half g_Mb[2*PP*DD];
__device__ int    g_cnt[LEVE*PP];
__device__ int    g_rp[LEVE*(PP+1)];
__device__ int    g_fill[LEVE*PP];
__device__ int    g_col[LEVE*PKE];
__device__ unsigned g_bars[64];

// fp16 fragment layouts:
// A: 64r x 128k halves. Blocks (mb in [0,4), kb in [0,8)), 132-word pitch.
//    word-in-block = lane*4 + reg, lane = (r&7)*4 + t, reg = 2*sel + hi
//    (t = (kl>>1)&3, sel = kl>>3, hi = (r>>3)&1, kl = k&15)
#define A_FRAG_SZ (32*132)            // 4224 words
// W: 128k x 128c halves. Blocks (cb in [0,16), kb in [0,8)), 66-word pitch.
//    word-in-block = ((c&7)*4 + t)*2 + sel
#define W_FRAG_SZ (128*66)            // 8448 words
__device__ unsigned g_wf[6*W_FRAG_SZ];   // 0 f_pre, 1 f_upd, 2 b_pre, 3 b_upd, 4 nt_w1, 5 nt_w2

// ---------------- helpers ----------------
__device__ __forceinline__ unsigned h2u(float a, float b) {
    const __half2 h = __floats2half2_rn(a, b);
    return *(const unsigned*)&h;
}
__device__ __forceinline__ void mma16(float* d, const unsigned* a, const unsigned* b) {
    asm("mma.sync.aligned.m16n8k16.row.col.f32.f16.f16.f32 "
        "{%0,%1,%2,%3},{%4,%5,%6,%7},{%8,%9},{%0,%1,%2,%3};"
        : "+f"(d[0]), "+f"(d[1]), "+f"(d[2]), "+f"(d[3])
        : "r"(a[0]), "r"(a[1]), "r"(a[2]), "r"(a[3]), "r"(b[0]), "r"(b[1]));
}
// store 8 consecutive columns (k = 8*c8 ..) of row r
__device__ __forceinline__ void frag_storeA8(unsigned* sA, int r, int c8, const float* f) {
    unsigned* p = sA + (((r>>4)*8 + (c8>>1))*132) + ((r&7)*16) + 2*(c8&1) + ((r>>3)&1);
    p[0] = h2u(f[0],f[1]); p[4] = h2u(f[2],f[3]);
    p[8] = h2u(f[4],f[5]); p[12] = h2u(f[6],f[7]);
}
// store one half2 at (r, c) with c even
__device__ __forceinline__ void frag_storeA_h2(unsigned* sA, int r, int c, unsigned h2) {
    const int kl = c & 15;
    sA[(((r>>4)*8 + (c>>4))*132) + ((r&7)*16) + ((kl>>1)&3)*4 + 2*(kl>>3) + ((r>>3)&1)] = h2;
}

// ---------------- prep: fp16 W fragments + CSR count + barrier zero ----------------
#define CNTB 290
__global__ void prep_kernel(const float* w0, const float* w1, const float* w2,
                            const float* w3, const float* w4, const float* w5,
                            const int* __restrict__ src) {
    const int tid = threadIdx.x;
    if (blockIdx.x < 6) {
        const float* W;
        switch (blockIdx.x) {
            case 0: W = w0; break; case 1: W = w1; break; case 2: W = w2; break;
            case 3: W = w3; break; case 4: W = w4; break; default: W = w5; break;
        }
        __half* dh = (__half*)(g_wf + (size_t)blockIdx.x * W_FRAG_SZ);
        #pragma unroll
        for (int it = 0; it < 16; ++it) {
            const int idx = tid + 256*it;
            const int k = idx >> 5, c4 = idx & 31;
            const float4 v = ((const float4*)W)[idx];
            const float vv[4] = {v.x, v.y, v.z, v.w};
            const int kb = k >> 4, kl = k & 15;
            const int t = (kl >> 1) & 3, sel = kl >> 3;
            #pragma unroll
            for (int q = 0; q < 4; ++q) {
                const int c = c4*4 + q;
                const int word = ((c>>3)*8 + kb)*66 + ((c&7)*4 + t)*2 + sel;
                dh[word*2 + (k&1)] = __float2half(vv[q]);
            }
        }
        if (blockIdx.x == 0 && tid < 64) g_bars[tid] = 0;
    } else {
        const int b = blockIdx.x - 6;
        const int tot = LEVE*PKE;
        for (int e = b*256 + tid; e < tot; e += CNTB*256)
            atomicAdd(&g_cnt[(e >> 16)*PP + src[e]], 1);
    }
}

// ---------------- fp16 GEMM core: 64x128 tile, 8 warps (wm in [0,2), wn in [0,4)) ----------------
__device__ __forceinline__ void gemm16(const unsigned* __restrict__ sA,
                                       const unsigned* __restrict__ sW,
                                       int wm, int wn, int lane,
                                       float acc[2][4][4]) {
    #pragma unroll
    for (int i = 0; i < 2; ++i)
        #pragma unroll
        for (int j = 0; j < 4; ++j)
            #pragma unroll
            for (int q = 0; q < 4; ++q) acc[i][j][q] = 0.f;
    #pragma unroll
    for (int kb = 0; kb < 8; ++kb) {
        unsigned a[2][4];
        #pragma unroll
        for (int i = 0; i < 2; ++i) {
            const uint4 v = *(const uint4*)(sA + (((wm*2+i)*8 + kb)*132) + lane*4);
            a[i][0] = v.x; a[i][1] = v.y; a[i][2] = v.z; a[i][3] = v.w;
        }
        unsigned b[4][2];
        #pragma unroll
        for (int j = 0; j < 4; ++j) {
            const uint2 v = *(const uint2*)(sW + (((wn*4+j)*8 + kb)*66) + lane*2);
            b[j][0] = v.x; b[j][1] = v.y;
        }
        #pragma unroll
        for (int i = 0; i < 2; ++i)
            #pragma unroll
            for (int j = 0; j < 4; ++j)
                mma16(acc[i][j], a[i], b[j]);
    }
}

#define WG_BAR() asm volatile("bar.sync %0, 256;" :: "r"(1+wg) : "memory")

// ---------------- node transform: 256-thread blocks, 64 rows each + CSR scan ----------------
#define NT_SMEM ((2*W_FRAG_SZ + A_FRAG_SZ + 256) * 4)

__global__ __launch_bounds__(256) void nt_fused(
    const float* __restrict__ x,
    const float* __restrict__ b1v, const float* __restrict__ b2v,
    float* __restrict__ Out)
{
    extern __shared__ unsigned sm[];
    const int tid = threadIdx.x;

    if (blockIdx.x >= NTB3) {            // 15 CSR scan blocks
        const int lvl = blockIdx.x - NTB3;
        const int base = lvl*PP;
        int c[32]; int sum = 0;
        #pragma unroll
        for (int j = 0; j < 32; ++j) { c[j] = g_cnt[base + tid*32 + j]; sum += c[j]; }
        int* sh = (int*)sm;
        sh[tid] = sum; __syncthreads();
        for (int d = 1; d < 256; d <<= 1) {
            int v = (tid >= d) ? sh[tid-d] : 0;
            __syncthreads();
            sh[tid] += v;
            __syncthreads();
        }
        int off = sh[tid] - sum;
        int* rpl = g_rp + lvl*(PP+1);
        #pragma unroll
        for (int j = 0; j < 32; ++j) {
            const int idx = tid*32 + j;
            rpl[idx] = off; g_fill[base + idx] = off; off += c[j];
        }
        if (tid == 255) rpl[PP] = off;
        return;
    }

    unsigned* sW1 = sm;
    unsigned* sW2 = sm + W_FRAG_SZ;
    unsigned* sA  = sm + 2*W_FRAG_SZ;
    float*    sB  = (float*)(sA + A_FRAG_SZ);
    const int lane = tid & 31, w = tid >> 5;
    const int wm = w >> 2, wn = w & 3;
    const int g = lane >> 2, t = lane & 3;
    const int r0 = blockIdx.x * 64;

    for (int i = tid; i < W_FRAG_SZ/4; i += 256) {
        ((uint4*)sW1)[i] = ((const uint4*)(g_wf + (size_t)4*W_FRAG_SZ))[i];
        ((uint4*)sW2)[i] = ((const uint4*)(g_wf + (size_t)5*W_FRAG_SZ))[i];
    }
    if (tid < 32) {
        ((float4*)sB)[tid]       = ((const float4*)b1v)[tid];
        ((float4*)(sB+128))[tid] = ((const float4*)b2v)[tid];
    }
    __syncthreads();

    // stage x (64 rows x 16 c8)
    #pragma unroll
    for (int it = 0; it < 4; ++it) {
        const int idx = tid + 256*it;
        const int r = idx >> 4, c8 = idx & 15;
        const float4 va = *(const float4*)(x + (size_t)(r0 + r)*128 + c8*8);
        const float4 vb = *(const float4*)(x + (size_t)(r0 + r)*128 + c8*8 + 4);
        const float f[8] = {va.x,va.y,va.z,va.w, vb.x,vb.y,vb.z,vb.w};
        frag_storeA8(sA, r, c8, f);
    }
    __syncthreads();
    float acc[2][4][4];
    gemm16(sA, sW1, wm, wn, lane, acc);
    __syncthreads();
    #pragma unroll
    for (int i = 0; i < 2; ++i) {
        const int rloc = wm*32 + i*16 + g;
        #pragma unroll
        for (int j = 0; j < 4; ++j) {
            const int c = wn*32 + j*8 + t*2;
            const float b0 = sB[c], b1 = sB[c+1];
            frag_storeA_h2(sA, rloc,   c, h2u(fmaxf(acc[i][j][0]+b0,0.f), fmaxf(acc[i][j][1]+b1,0.f)));
            frag_storeA_h2(sA, rloc+8, c, h2u(fmaxf(acc[i][j][2]+b0,0.f), fmaxf(acc[i][j][3]+b1,0.f)));
        }
    }
    __syncthreads();
    float acc2[2][4][4];
    gemm16(sA, sW2, wm, wn, lane, acc2);
    #pragma unroll
    for (int i = 0; i < 2; ++i) {
        const int rl = r0 + wm*32 + i*16 + g;
        #pragma unroll
        for (int j = 0; j < 4; ++j) {
            const int c = wn*32 + j*8 + t*2;
            const float b0 = sB[128+c], b1 = sB[128+c+1];
            *(float2*)(Out + (size_t)rl*128 + c)
                = make_float2(acc2[i][j][0]+b0, acc2[i][j][1]+b1);
            *(float2*)(Out + (size_t)(rl+8)*128 + c)
                = make_float2(acc2[i][j][2]+b0, acc2[i][j][3]+b1);
        }
    }
}

// ---------------- split grid sync ----------------
__device__ __forceinline__ void g_arrive(unsigned* ctr) {
    __syncthreads();
    __threadfence();
    if (threadIdx.x == 0) atomicAdd(ctr, 1u);
}
__device__ __forceinline__ void g_wait(unsigned* ctr, unsigned tgt) {
    if (threadIdx.x == 0) {
        unsigned v;
        do {
            asm volatile("ld.acquire.gpu.global.u32 %0, [%1];" : "=r"(v) : "l"(ctr) : "memory");
        } while (v < tgt);
    }
    __syncthreads();
}

__device__ __forceinline__ void acc8(float* f, uint4 u) {
    const float2 a = __half22float2(*(const __half2*)&u.x);
    const float2 b = __half22float2(*(const __half2*)&u.y);
    const float2 c = __half22float2(*(const __half2*)&u.z);
    const float2 d = __half22float2(*(const __half2*)&u.w);
    f[0]+=a.x; f[1]+=a.y; f[2]+=b.x; f[3]+=b.y;
    f[4]+=c.x; f[5]+=c.y; f[6]+=d.x; f[7]+=d.y;
}

// ---------------- persistent dual-chain message-passing kernel ----------------
#define CH_SMEM ((2*W_FRAG_SZ + 2*A_FRAG_SZ + 256) * 4)

__global__ __launch_bounds__(512, 1) void chain_kernel(
    float* __restrict__ out,
    const int* __restrict__ src,
    const float* __restrict__ f_pre_b, const float* __restrict__ f_upd_b,
    const float* __restrict__ b_pre_b, const float* __restrict__ b_upd_b)
{
    extern __shared__ unsigned sm[];
    unsigned* sWpre = sm;
    unsigned* sWupd = sm + W_FRAG_SZ;
    unsigned* sA0   = sm + 2*W_FRAG_SZ;
    unsigned* sA1   = sA0 + A_FRAG_SZ;
    float*    sB    = (float*)(sA1 + A_FRAG_SZ);

    const int tid = threadIdx.x, lane = tid & 31, w = tid >> 5;
    const int wg = w >> 3, lt = tid & 255;
    const int wm = (w >> 2) & 1, wn = w & 3;
    const int g = lane >> 2, t = lane & 3;
    const bool fwd = blockIdx.x < CH;
    const int cc = fwd ? blockIdx.x : blockIdx.x - CH;
    const int r0 = cc * 128;
    const int cofs = fwd ? 0 : 128;
    unsigned* ctr = &g_bars[fwd ? 0 : 32];
    __half* Mbase = fwd ? g_Mf : g_Mb;
    const unsigned* wfpre = g_wf + (size_t)(fwd ? 0 : 2) * W_FRAG_SZ;
    const unsigned* wfupd = g_wf + (size_t)(fwd ? 1 : 3) * W_FRAG_SZ;
    const float* preB = fwd ? f_pre_b : b_pre_b;
    const float* updB = fwd ? f_upd_b : b_upd_b;
    unsigned* sAw = wg ? sA1 : sA0;

    if (!fwd) {
        const int tot = LEVE*PKE;
        for (int e = cc*512 + tid; e < tot; e += CH*512) {
            const int lvl = e >> 16;
            const int le  = e & (PKE-1);
            const int pos = atomicAdd(&g_fill[lvl*PP + src[e]], 1);
            g_col[(size_t)lvl*PKE + pos] = le >> 3;
        }
    }

    for (int i = tid; i < W_FRAG_SZ/4; i += 512) {
        ((uint4*)sWpre)[i] = ((const uint4*)wfpre)[i];
        ((uint4*)sWupd)[i] = ((const uint4*)wfupd)[i];
    }
    if (tid < 32) {
        ((float4*)sB)[tid]       = ((const float4*)preB)[tid];
        ((float4*)(sB+128))[tid] = ((const float4*)updB)[tid];
    }
    __syncthreads();

    unsigned tgt = 0;
    // ---- boundary level ----
    {
        const int lvl0 = fwd ? 0 : LEVE;
        float4 y0[8];
        #pragma unroll
        for (int it = 0; it < 4; ++it) {
            const int idx = lt + 256*it;
            const int r = idx >> 4, c8 = idx & 15;
            const size_t node = (size_t)lvl0*PP + r0 + wg*64 + r;
            const float* hv = g_h + node*128 + c8*8;
            const float* ub = sB + 128 + c8*8;
            float f[8];
            #pragma unroll
            for (int q = 0; q < 8; ++q) f[q] = fmaxf(ub[q], 0.f) + hv[q];
            y0[2*it]   = make_float4(f[0],f[1],f[2],f[3]);
            y0[2*it+1] = make_float4(f[4],f[5],f[6],f[7]);
            frag_storeA8(sAw, r, c8, f);
        }
        WG_BAR();
        const int l1 = fwd ? 1 : (LEVE-1);
        __half* Mnext = Mbase + (size_t)(l1 & 1)*PP*DD;
        float acc[2][4][4];
        gemm16(sAw, sWpre, wm, wn, lane, acc);
        #pragma unroll
        for (int i = 0; i < 2; ++i) {
            const int rl = r0 + wg*64 + wm*32 + i*16 + g;
            #pragma unroll
            for (int j = 0; j < 4; ++j) {
                const int c = wn*32 + j*8 + t*2;
                const float b0 = sB[c], b1 = sB[c+1];
                *(__half2*)(Mnext + (size_t)rl*128 + c) =
                    __floats2half2_rn(fmaxf(acc[i][j][0]+b0,0.f), fmaxf(acc[i][j][1]+b1,0.f));
                *(__half2*)(Mnext + (size_t)(rl+8)*128 + c) =
                    __floats2half2_rn(fmaxf(acc[i][j][2]+b0,0.f), fmaxf(acc[i][j][3]+b1,0.f));
            }
        }
        tgt += CH;
        g_arrive(ctr);
        #pragma unroll
        for (int it = 0; it < 4; ++it) {
            const int idx = lt + 256*it;
            const int r = idx >> 4, c8 = idx & 15;
            const size_t node = (size_t)lvl0*PP + r0 + wg*64 + r;
            *(float4*)(out + node*256 + cofs + c8*8)     = y0[2*it];
            *(float4*)(out + node*256 + cofs + c8*8 + 4) = y0[2*it+1];
        }
        g_wait(ctr, tgt);
    }

    for (int s = 0; s < LEVE; ++s) {
        const int l = fwd ? (1+s) : (LEVE-1-s);
        const bool last = (s == LEVE-1);
        __half* Mbuf = Mbase + (size_t)(l & 1)*PP*DD;

        // ---- gather-mean of M into sAw ----
        #pragma unroll
        for (int it = 0; it < 4; ++it) {
            const int idx = lt + 256*it;
            const int r = idx >> 4, c8 = idx & 15;
            const int pl = r0 + wg*64 + r;
            float f[8];
            #pragma unroll
            for (int q = 0; q < 8; ++q) f[q] = 0.f;
            float inv = 0.125f;
            if (fwd) {
                const int4* sp = (const int4*)(src + (size_t)(l-1)*PKE + pl*KK);
                const int4 ia = sp[0], ib = sp[1];
                acc8(f, *(const uint4*)(Mbuf + (size_t)ia.x*128 + c8*8));
                acc8(f, *(const uint4*)(Mbuf + (size_t)ia.y*128 + c8*8));
                acc8(f, *(const uint4*)(Mbuf + (size_t)ia.z*128 + c8*8));
                acc8(f, *(const uint4*)(Mbuf + (size_t)ia.w*128 + c8*8));
                acc8(f, *(const uint4*)(Mbuf + (size_t)ib.x*128 + c8*8));
                acc8(f, *(const uint4*)(Mbuf + (size_t)ib.y*128 + c8*8));
                acc8(f, *(const uint4*)(Mbuf + (size_t)ib.z*128 + c8*8));
                acc8(f, *(const uint4*)(Mbuf + (size_t)ib.w*128 + c8*8));
            } else {
                const int* rpl = g_rp + l*(PP+1);
                const int b0 = rpl[pl], e0 = rpl[pl+1];
                const int* colsl = g_col + (size_t)l*PKE;
                int jj = b0;
                for (; jj + 2 <= e0; jj += 2) {
                    const int d0 = colsl[jj], d1 = colsl[jj+1];
                    const uint4 u0 = *(const uint4*)(Mbuf + (size_t)d0*128 + c8*8);
                    const uint4 u1 = *(const uint4*)(Mbuf + (size_t)d1*128 + c8*8);
                    acc8(f, u0); acc8(f, u1);
                }
                if (jj < e0)
                    acc8(f, *(const uint4*)(Mbuf + (size_t)colsl[jj]*128 + c8*8));
                inv = (e0 > b0) ? 1.0f/(float)(e0-b0) : 0.f;
            }
            #pragma unroll
            for (int q = 0; q < 8; ++q) f[q] *= inv;
            frag_storeA8(sAw, r, c8, f);
        }
        WG_BAR();

        // ---- update GEMM ----
        float acc[2][4][4];
        gemm16(sAw, sWupd, wm, wn, lane, acc);
        WG_BAR();

        // ---- epilogue: Y = relu(acc+updB)+h; keep Y in acc; frags for preGEMM ----
        #pragma unroll
        for (int i = 0; i < 2; ++i) {
            const int rloc = wm*32 + i*16 + g;
            const int rl = r0 + wg*64 + rloc;
            #pragma unroll
            for (int j = 0; j < 4; ++j) {
                const int c = wn*32 + j*8 + t*2;
                const float b0 = sB[128+c], b1 = sB[128+c+1];
                float v0 = fmaxf(acc[i][j][0]+b0, 0.f);
                float v1 = fmaxf(acc[i][j][1]+b1, 0.f);
                float v2 = fmaxf(acc[i][j][2]+b0, 0.f);
                float v3 = fmaxf(acc[i][j][3]+b1, 0.f);
                const size_t nlo = (size_t)l*PP + rl, nhi = nlo + 8;
                const float2 hlo = *(const float2*)(g_h + nlo*128 + c);
                const float2 hhi = *(const float2*)(g_h + nhi*128 + c);
                v0 += hlo.x; v1 += hlo.y; v2 += hhi.x; v3 += hhi.y;
                if (!last) {
                    frag_storeA_h2(sAw, rloc,   c, h2u(v0, v1));
                    frag_storeA_h2(sAw, rloc+8, c, h2u(v2, v3));
                }
                acc[i][j][0] = v0; acc[i][j][1] = v1;
                acc[i][j][2] = v2; acc[i][j][3] = v3;
            }
        }

        if (!last) {
            WG_BAR();
            const int lnext = fwd ? (l+1) : (l-1);
            __half* Mnext = Mbase + (size_t)(lnext & 1)*PP*DD;
            float acc2[2][4][4];
            gemm16(sAw, sWpre, wm, wn, lane, acc2);
            #pragma unroll
            for (int i = 0; i < 2; ++i) {
                const int rl = r0 + wg*64 + wm*32 + i*16 + g;
                #pragma unroll
                for (int j = 0; j < 4; ++j) {
                    const int c = wn*32 + j*8 + t*2;
                    const float b0 = sB[c], b1 = sB[c+1];
                    *(__half2*)(Mnext + (size_t)rl*128 + c) =
                        __floats2half2_rn(fmaxf(acc2[i][j][0]+b0,0.f), fmaxf(acc2[i][j][1]+b1,0.f));
                    *(__half2*)(Mnext + (size_t)(rl+8)*128 + c) =
                        __floats2half2_rn(fmaxf(acc2[i][j][2]+b0,0.f), fmaxf(acc2[i][j][3]+b1,0.f));
                }
            }
            tgt += CH;
            g_arrive(ctr);
        }

        // ---- out-write from Y held in acc ----
        #pragma unroll
        for (int i = 0; i < 2; ++i) {
            const int rl = r0 + wg*64 + wm*32 + i*16 + g;
            #pragma unroll
            for (int j = 0; j < 4; ++j) {
                const int c = wn*32 + j*8 + t*2;
                const size_t nlo = (size_t)l*PP + rl, nhi = nlo + 8;
                *(float2*)(out + nlo*256 + cofs + c) = make_float2(acc[i][j][0], acc[i][j][1]);
                *(float2*)(out + nhi*256 + cofs + c) = make_float2(acc[i][j][2], acc[i][j][3]);
            }
        }

        if (!last) g_wait(ctr, tgt);
    }
}

// ---------------- launch ----------------
extern "C" void kernel_launch(void* const* d_in, const int* in_sizes, int n_in,
                              void* d_out, int out_size) {
    const float* x       = (const float*)d_in[0];
    const int*   src     = (const int*)  d_in[1];
    const float* nt_w1   = (const float*)d_in[2];
    const float* nt_b1   = (const float*)d_in[3];
    const float* nt_w2   = (const float*)d_in[4];
    const float* nt_b2   = (const float*)d_in[5];
    const float* f_pre_w = (const float*)d_in[6];
    const float* f_pre_b = (const float*)d_in[7];
    const float* f_upd_w = (const float*)d_in[8];
    const float* f_upd_b = (const float*)d_in[9];
    const float* b_pre_w = (const float*)d_in[10];
    const float* b_pre_b = (const float*)d_in[11];
    const float* b_upd_w = (const float*)d_in[12];
    const float* b_upd_b = (const float*)d_in[13];
    float* out = (float*)d_out;

    void *p_h, *p_cnt;
    cudaGetSymbolAddress(&p_h,   g_h);
    cudaGetSymbolAddress(&p_cnt, g_cnt);

    cudaFuncSetAttribute(nt_fused,     cudaFuncAttributeMaxDynamicSharedMemorySize, NT_SMEM);
    cudaFuncSetAttribute(chain_kernel, cudaFuncAttributeMaxDynamicSharedMemorySize, CH_SMEM);

    float* h = (float*)p_h;

    cudaMemsetAsync(p_cnt, 0, (size_t)LEVE*PP*sizeof(int));
    prep_kernel<<<6 + CNTB, 256>>>(f_pre_w, f_upd_w, b_pre_w, b_upd_w, nt_w1, nt_w2, src);
    nt_fused<<<NTB3 + LEVE, 256, NT_SMEM>>>(x, nt_b1, nt_b2, h);
    chain_kernel<<<2*CH, 512, CH_SMEM>>>(out, src,
        f_pre_b, f_upd_b, b_pre_b, b_upd_b);
}

// round 11
// speedup vs baseline: 1.5950x; 1.0339x over previous
#include <cuda_runtime.h>
#include <cuda_fp16.h>
#include <cstdint>

#define NN 131072
#define DD 128
#define LL 16
#define PP 8192
#define KK 8
#define PKE (PP*KK)
#define LEVE (LL-1)
#define CH 64            // CTAs per chain
#define FWD_Q 11         // NT 64-row tiles per fwd warp-group
#define REV_Q 5          // NT tiles per rev warp-group (128*11 + 128*5 = 2048)

// ---------------- scratch ----------------
__device__ float  g_h[(size_t)NN*DD];
__device__ __half g_Mf[2*PP*DD];
__device__ __half g_Mb[2*PP*DD];
__device__ int    g_cnt[LEVE*PP];
__device__ int    g_rp[LEVE*(PP+1)];
__device__ int    g_fill[LEVE*PP];
__device__ int    g_col[LEVE*PKE];
__device__ unsigned g_bars[64];   // 0: fwd, 32: rev, 16: joint NT barrier

// fp16 fragment layouts (see round-10 derivation)
#define A_FRAG_SZ (32*132)            // 4224 words
#define W_FRAG_SZ (128*66)            // 8448 words
__device__ unsigned g_wf[6*W_FRAG_SZ];   // 0 f_pre, 1 f_upd, 2 b_pre, 3 b_upd, 4 nt_w1, 5 nt_w2

// ---------------- helpers ----------------
__device__ __forceinline__ unsigned h2u(float a, float b) {
    const __half2 h = __floats2half2_rn(a, b);
    return *(const unsigned*)&h;
}
__device__ __forceinline__ void mma16(float* d, const unsigned* a, const unsigned* b) {
    asm("mma.sync.aligned.m16n8k16.row.col.f32.f16.f16.f32 "
        "{%0,%1,%2,%3},{%4,%5,%6,%7},{%8,%9},{%0,%1,%2,%3};"
        : "+f"(d[0]), "+f"(d[1]), "+f"(d[2]), "+f"(d[3])
        : "r"(a[0]), "r"(a[1]), "r"(a[2]), "r"(a[3]), "r"(b[0]), "r"(b[1]));
}
__device__ __forceinline__ void frag_storeA8(unsigned* sA, int r, int c8, const float* f) {
    unsigned* p = sA + (((r>>4)*8 + (c8>>1))*132) + ((r&7)*16) + 2*(c8&1) + ((r>>3)&1);
    p[0] = h2u(f[0],f[1]); p[4] = h2u(f[2],f[3]);
    p[8] = h2u(f[4],f[5]); p[12] = h2u(f[6],f[7]);
}
__device__ __forceinline__ void frag_storeA_h2(unsigned* sA, int r, int c, unsigned h2) {
    const int kl = c & 15;
    sA[(((r>>4)*8 + (c>>4))*132) + ((r&7)*16) + ((kl>>1)&3)*4 + 2*(kl>>3) + ((r>>3)&1)] = h2;
}
__device__ __forceinline__ void acc8(float* f, uint4 u) {
    const float2 a = __half22float2(*(const __half2*)&u.x);
    const float2 b = __half22float2(*(const __half2*)&u.y);
    const float2 c = __half22float2(*(const __half2*)&u.z);
    const float2 d = __half22float2(*(const __half2*)&u.w);
    f[0]+=a.x; f[1]+=a.y; f[2]+=b.x; f[3]+=b.y;
    f[4]+=c.x; f[5]+=c.y; f[6]+=d.x; f[7]+=d.y;
}

// ---------------- prep: fp16 W fragments + CSR count + barrier zero ----------------
#define CNTB 290
__global__ void prep_kernel(const float* w0, const float* w1, const float* w2,
                            const float* w3, const float* w4, const float* w5,
                            const int* __restrict__ src) {
    const int tid = threadIdx.x;
    if (blockIdx.x < 6) {
        const float* W;
        switch (blockIdx.x) {
            case 0: W = w0; break; case 1: W = w1; break; case 2: W = w2; break;
            case 3: W = w3; break; case 4: W = w4; break; default: W = w5; break;
        }
        __half* dh = (__half*)(g_wf + (size_t)blockIdx.x * W_FRAG_SZ);
        #pragma unroll
        for (int it = 0; it < 16; ++it) {
            const int idx = tid + 256*it;
            const int k = idx >> 5, c4 = idx & 31;
            const float4 v = ((const float4*)W)[idx];
            const float vv[4] = {v.x, v.y, v.z, v.w};
            const int kb = k >> 4, kl = k & 15;
            const int t = (kl >> 1) & 3, sel = kl >> 3;
            #pragma unroll
            for (int q = 0; q < 4; ++q) {
                const int c = c4*4 + q;
                const int word = ((c>>3)*8 + kb)*66 + ((c&7)*4 + t)*2 + sel;
                dh[word*2 + (k&1)] = __float2half(vv[q]);
            }
        }
        if (blockIdx.x == 0 && tid < 64) g_bars[tid] = 0;
    } else {
        const int b = blockIdx.x - 6;
        const int tot = LEVE*PKE;
        for (int e = b*256 + tid; e < tot; e += CNTB*256)
            atomicAdd(&g_cnt[(e >> 16)*PP + src[e]], 1);
    }
}

// ---------------- fp16 GEMM core: 64x128 tile, 8 warps ----------------
__device__ __forceinline__ void gemm16(const unsigned* __restrict__ sA,
                                       const unsigned* __restrict__ sW,
                                       int wm, int wn, int lane,
                                       float acc[2][4][4]) {
    #pragma unroll
    for (int i = 0; i < 2; ++i)
        #pragma unroll
        for (int j = 0; j < 4; ++j)
            #pragma unroll
            for (int q = 0; q < 4; ++q) acc[i][j][q] = 0.f;
    #pragma unroll
    for (int kb = 0; kb < 8; ++kb) {
        unsigned a[2][4];
        #pragma unroll
        for (int i = 0; i < 2; ++i) {
            const uint4 v = *(const uint4*)(sA + (((wm*2+i)*8 + kb)*132) + lane*4);
            a[i][0] = v.x; a[i][1] = v.y; a[i][2] = v.z; a[i][3] = v.w;
        }
        unsigned b[4][2];
        #pragma unroll
        for (int j = 0; j < 4; ++j) {
            const uint2 v = *(const uint2*)(sW + (((wn*4+j)*8 + kb)*66) + lane*2);
            b[j][0] = v.x; b[j][1] = v.y;
        }
        #pragma unroll
        for (int i = 0; i < 2; ++i)
            #pragma unroll
            for (int j = 0; j < 4; ++j)
                mma16(acc[i][j], a[i], b[j]);
    }
}

#define WG_BAR() asm volatile("bar.sync %0, 256;" :: "r"(1+wg) : "memory")

// ---------------- split grid sync ----------------
__device__ __forceinline__ void g_arrive(unsigned* ctr) {
    __syncthreads();
    __threadfence();
    if (threadIdx.x == 0) atomicAdd(ctr, 1u);
}
__device__ __forceinline__ void g_wait(unsigned* ctr, unsigned tgt) {
    if (threadIdx.x == 0) {
        unsigned v;
        do {
            asm volatile("ld.acquire.gpu.global.u32 %0, [%1];" : "=r"(v) : "l"(ctr) : "memory");
        } while (v < tgt);
    }
    __syncthreads();
}

// ---------------- mega persistent kernel: CSR scan/fill + NT + both MP chains ----------------
#define CH_SMEM ((2*W_FRAG_SZ + 2*A_FRAG_SZ + 256) * 4)

__global__ __launch_bounds__(512, 1) void mega_kernel(
    float* __restrict__ out,
    const float* __restrict__ x,
    const int* __restrict__ src,
    const float* __restrict__ nt_b1, const float* __restrict__ nt_b2,
    const float* __restrict__ f_pre_b, const float* __restrict__ f_upd_b,
    const float* __restrict__ b_pre_b, const float* __restrict__ b_upd_b)
{
    extern __shared__ unsigned sm[];
    unsigned* sWpre = sm;                   // NT phase: W1 ; chain phase: pre_w
    unsigned* sWupd = sm + W_FRAG_SZ;       // NT phase: W2 ; chain phase: upd_w
    unsigned* sA0   = sm + 2*W_FRAG_SZ;
    unsigned* sA1   = sA0 + A_FRAG_SZ;
    float*    sB    = (float*)(sA1 + A_FRAG_SZ);

    const int tid = threadIdx.x, lane = tid & 31, w = tid >> 5;
    const int wg = w >> 3, lt = tid & 255;
    const int wm = (w >> 2) & 1, wn = w & 3;
    const int g = lane >> 2, t = lane & 3;
    const bool fwd = blockIdx.x < CH;
    const int cc = fwd ? blockIdx.x : blockIdx.x - CH;
    const int r0 = cc * 128;
    const int cofs = fwd ? 0 : 128;
    unsigned* ctr = &g_bars[fwd ? 0 : 32];
    __half* Mbase = fwd ? g_Mf : g_Mb;
    const unsigned* wfpre = g_wf + (size_t)(fwd ? 0 : 2) * W_FRAG_SZ;
    const unsigned* wfupd = g_wf + (size_t)(fwd ? 1 : 3) * W_FRAG_SZ;
    const float* preB = fwd ? f_pre_b : b_pre_b;
    const float* updB = fwd ? f_upd_b : b_upd_b;
    unsigned* sAw = wg ? sA1 : sA0;

    unsigned tgt = 0;

    // ============ rev CTAs: CSR scan (CTAs 0..14) + rev-sync + fill ============
    if (!fwd) {
        if (cc < LEVE) {
            const int lvl = cc;
            const int base = lvl*PP;
            int c[16]; int sum = 0;
            #pragma unroll
            for (int j = 0; j < 16; ++j) { c[j] = g_cnt[base + tid*16 + j]; sum += c[j]; }
            int* sh = (int*)sA0;
            sh[tid] = sum; __syncthreads();
            for (int d = 1; d < 512; d <<= 1) {
                int v = (tid >= d) ? sh[tid-d] : 0;
                __syncthreads();
                sh[tid] += v;
                __syncthreads();
            }
            int off = sh[tid] - sum;
            int* rpl = g_rp + lvl*(PP+1);
            #pragma unroll
            for (int j = 0; j < 16; ++j) {
                const int idx = tid*16 + j;
                rpl[idx] = off; g_fill[base + idx] = off; off += c[j];
            }
            if (tid == 511) rpl[PP] = off;
        }
        tgt += CH;
        g_arrive(ctr);
        g_wait(ctr, tgt);
        // fill (published by joint NT barrier below)
        const int tot = LEVE*PKE;
        for (int e = cc*512 + tid; e < tot; e += CH*512) {
            const int lvl = e >> 16;
            const int le  = e & (PKE-1);
            const int pos = atomicAdd(&g_fill[lvl*PP + src[e]], 1);
            g_col[(size_t)lvl*PKE + pos] = le >> 3;
        }
    }

    // ============ node transform section ============
    for (int i = tid; i < W_FRAG_SZ/4; i += 512) {
        ((uint4*)sWpre)[i] = ((const uint4*)(g_wf + (size_t)4*W_FRAG_SZ))[i];
        ((uint4*)sWupd)[i] = ((const uint4*)(g_wf + (size_t)5*W_FRAG_SZ))[i];
    }
    if (tid < 32) {
        ((float4*)sB)[tid]       = ((const float4*)nt_b1)[tid];
        ((float4*)(sB+128))[tid] = ((const float4*)nt_b2)[tid];
    }
    __syncthreads();

    {
        const int gid = cc*2 + wg;
        const int tq = fwd ? FWD_Q : REV_Q;
        const int tb = fwd ? gid*FWD_Q : (128*FWD_Q + gid*REV_Q);
        for (int i = 0; i < tq; ++i) {
            const int rn = (tb + i) * 64;
            #pragma unroll
            for (int it = 0; it < 4; ++it) {
                const int idx = lt + 256*it;
                const int r = idx >> 4, c8 = idx & 15;
                const float4 va = *(const float4*)(x + (size_t)(rn + r)*128 + c8*8);
                const float4 vb = *(const float4*)(x + (size_t)(rn + r)*128 + c8*8 + 4);
                const float f[8] = {va.x,va.y,va.z,va.w, vb.x,vb.y,vb.z,vb.w};
                frag_storeA8(sAw, r, c8, f);
            }
            WG_BAR();
            float acc[2][4][4];
            gemm16(sAw, sWpre, wm, wn, lane, acc);
            WG_BAR();
            #pragma unroll
            for (int ii = 0; ii < 2; ++ii) {
                const int rloc = wm*32 + ii*16 + g;
                #pragma unroll
                for (int j = 0; j < 4; ++j) {
                    const int c = wn*32 + j*8 + t*2;
                    const float b0 = sB[c], b1 = sB[c+1];
                    frag_storeA_h2(sAw, rloc,   c, h2u(fmaxf(acc[ii][j][0]+b0,0.f), fmaxf(acc[ii][j][1]+b1,0.f)));
                    frag_storeA_h2(sAw, rloc+8, c, h2u(fmaxf(acc[ii][j][2]+b0,0.f), fmaxf(acc[ii][j][3]+b1,0.f)));
                }
            }
            WG_BAR();
            float acc2[2][4][4];
            gemm16(sAw, sWupd, wm, wn, lane, acc2);
            #pragma unroll
            for (int ii = 0; ii < 2; ++ii) {
                const int rl = rn + wm*32 + ii*16 + g;
                #pragma unroll
                for (int j = 0; j < 4; ++j) {
                    const int c = wn*32 + j*8 + t*2;
                    const float b0 = sB[128+c], b1 = sB[128+c+1];
                    *(float2*)(g_h + (size_t)rl*128 + c)
                        = make_float2(acc2[ii][j][0]+b0, acc2[ii][j][1]+b1);
                    *(float2*)(g_h + (size_t)(rl+8)*128 + c)
                        = make_float2(acc2[ii][j][2]+b0, acc2[ii][j][3]+b1);
                }
            }
            WG_BAR();
        }
    }

    // joint barrier across all 128 CTAs (publishes h + CSR fill);
    // chain weight copy overlaps the wait
    g_arrive(&g_bars[16]);
    for (int i = tid; i < W_FRAG_SZ/4; i += 512) {
        ((uint4*)sWpre)[i] = ((const uint4*)wfpre)[i];
        ((uint4*)sWupd)[i] = ((const uint4*)wfupd)[i];
    }
    if (tid < 32) {
        ((float4*)sB)[tid]       = ((const float4*)preB)[tid];
        ((float4*)(sB+128))[tid] = ((const float4*)updB)[tid];
    }
    g_wait(&g_bars[16], 2*CH);

    // ============ boundary level ============
    {
        const int lvl0 = fwd ? 0 : LEVE;
        float4 y0[8];
        #pragma unroll
        for (int it = 0; it < 4; ++it) {
            const int idx = lt + 256*it;
            const int r = idx >> 4, c8 = idx & 15;
            const size_t node = (size_t)lvl0*PP + r0 + wg*64 + r;
            const float* hv = g_h + node*128 + c8*8;
            const float* ub = sB + 128 + c8*8;
            float f[8];
            #pragma unroll
            for (int q = 0; q < 8; ++q) f[q] = fmaxf(ub[q], 0.f) + hv[q];
            y0[2*it]   = make_float4(f[0],f[1],f[2],f[3]);
            y0[2*it+1] = make_float4(f[4],f[5],f[6],f[7]);
            frag_storeA8(sAw, r, c8, f);
        }
        WG_BAR();
        const int l1 = fwd ? 1 : (LEVE-1);
        __half* Mnext = Mbase + (size_t)(l1 & 1)*PP*DD;
        float acc[2][4][4];
        gemm16(sAw, sWpre, wm, wn, lane, acc);
        #pragma unroll
        for (int i = 0; i < 2; ++i) {
            const int rl = r0 + wg*64 + wm*32 + i*16 + g;
            #pragma unroll
            for (int j = 0; j < 4; ++j) {
                const int c = wn*32 + j*8 + t*2;
                const float b0 = sB[c], b1 = sB[c+1];
                *(__half2*)(Mnext + (size_t)rl*128 + c) =
                    __floats2half2_rn(fmaxf(acc[i][j][0]+b0,0.f), fmaxf(acc[i][j][1]+b1,0.f));
                *(__half2*)(Mnext + (size_t)(rl+8)*128 + c) =
                    __floats2half2_rn(fmaxf(acc[i][j][2]+b0,0.f), fmaxf(acc[i][j][3]+b1,0.f));
            }
        }
        tgt += CH;
        g_arrive(ctr);
        #pragma unroll
        for (int it = 0; it < 4; ++it) {
            const int idx = lt + 256*it;
            const int r = idx >> 4, c8 = idx & 15;
            const size_t node = (size_t)lvl0*PP + r0 + wg*64 + r;
            *(float4*)(out + node*256 + cofs + c8*8)     = y0[2*it];
            *(float4*)(out + node*256 + cofs + c8*8 + 4) = y0[2*it+1];
        }
        g_wait(ctr, tgt);
    }

    // ============ 15 levels ============
    for (int s = 0; s < LEVE; ++s) {
        const int l = fwd ? (1+s) : (LEVE-1-s);
        const bool last = (s == LEVE-1);
        __half* Mbuf = Mbase + (size_t)(l & 1)*PP*DD;

        // ---- gather-mean of M into sAw ----
        #pragma unroll
        for (int it = 0; it < 4; ++it) {
            const int idx = lt + 256*it;
            const int r = idx >> 4, c8 = idx & 15;
            const int pl = r0 + wg*64 + r;
            float f[8];
            #pragma unroll
            for (int q = 0; q < 8; ++q) f[q] = 0.f;
            float inv = 0.125f;
            if (fwd) {
                const int4* sp = (const int4*)(src + (size_t)(l-1)*PKE + pl*KK);
                const int4 ia = sp[0], ib = sp[1];
                acc8(f, *(const uint4*)(Mbuf + (size_t)ia.x*128 + c8*8));
                acc8(f, *(const uint4*)(Mbuf + (size_t)ia.y*128 + c8*8));
                acc8(f, *(const uint4*)(Mbuf + (size_t)ia.z*128 + c8*8));
                acc8(f, *(const uint4*)(Mbuf + (size_t)ia.w*128 + c8*8));
                acc8(f, *(const uint4*)(Mbuf + (size_t)ib.x*128 + c8*8));
                acc8(f, *(const uint4*)(Mbuf + (size_t)ib.y*128 + c8*8));
                acc8(f, *(const uint4*)(Mbuf + (size_t)ib.z*128 + c8*8));
                acc8(f, *(const uint4*)(Mbuf + (size_t)ib.w*128 + c8*8));
            } else {
                const int* rpl = g_rp + l*(PP+1);
                const int b0 = rpl[pl], e0 = rpl[pl+1];
                const int* colsl = g_col + (size_t)l*PKE;
                int jj = b0;
                for (; jj + 4 <= e0; jj += 4) {
                    const int d0 = colsl[jj], d1 = colsl[jj+1];
                    const int d2 = colsl[jj+2], d3 = colsl[jj+3];
                    const uint4 u0 = *(const uint4*)(Mbuf + (size_t)d0*128 + c8*8);
                    const uint4 u1 = *(const uint4*)(Mbuf + (size_t)d1*128 + c8*8);
                    const uint4 u2 = *(const uint4*)(Mbuf + (size_t)d2*128 + c8*8);
                    const uint4 u3 = *(const uint4*)(Mbuf + (size_t)d3*128 + c8*8);
                    acc8(f, u0); acc8(f, u1); acc8(f, u2); acc8(f, u3);
                }
                for (; jj < e0; ++jj)
                    acc8(f, *(const uint4*)(Mbuf + (size_t)colsl[jj]*128 + c8*8));
                inv = (e0 > b0) ? 1.0f/(float)(e0-b0) : 0.f;
            }
            #pragma unroll
            for (int q = 0; q < 8; ++q) f[q] *= inv;
            frag_storeA8(sAw, r, c8, f);
        }
        WG_BAR();

        // ---- update GEMM ----
        float acc[2][4][4];
        gemm16(sAw, sWupd, wm, wn, lane, acc);
        WG_BAR();

        // ---- epilogue: Y = relu(acc+updB)+h; keep Y in acc; frags for preGEMM ----
        #pragma unroll
        for (int i = 0; i < 2; ++i) {
            const int rloc = wm*32 + i*16 + g;
            const int rl = r0 + wg*64 + rloc;
            #pragma unroll
            for (int j = 0; j < 4; ++j) {
                const int c = wn*32 + j*8 + t*2;
                const float b0 = sB[128+c], b1 = sB[128+c+1];
                float v0 = fmaxf(acc[i][j][0]+b0, 0.f);
                float v1 = fmaxf(acc[i][j][1]+b1, 0.f);
                float v2 = fmaxf(acc[i][j][2]+b0, 0.f);
                float v3 = fmaxf(acc[i][j][3]+b1, 0.f);
                const size_t nlo = (size_t)l*PP + rl, nhi = nlo + 8;
                const float2 hlo = *(const float2*)(g_h + nlo*128 + c);
                const float2 hhi = *(const float2*)(g_h + nhi*128 + c);
                v0 += hlo.x; v1 += hlo.y; v2 += hhi.x; v3 += hhi.y;
                if (!last) {
                    frag_storeA_h2(sAw, rloc,   c, h2u(v0, v1));
                    frag_storeA_h2(sAw, rloc+8, c, h2u(v2, v3));
                }
                acc[i][j][0] = v0; acc[i][j][1] = v1;
                acc[i][j][2] = v2; acc[i][j][3] = v3;
            }
        }

        if (!last) {
            WG_BAR();
            const int lnext = fwd ? (l+1) : (l-1);
            __half* Mnext = Mbase + (size_t)(lnext & 1)*PP*DD;
            float acc2[2][4][4];
            gemm16(sAw, sWpre, wm, wn, lane, acc2);
            #pragma unroll
            for (int i = 0; i < 2; ++i) {
                const int rl = r0 + wg*64 + wm*32 + i*16 + g;
                #pragma unroll
                for (int j = 0; j < 4; ++j) {
                    const int c = wn*32 + j*8 + t*2;
                    const float b0 = sB[c], b1 = sB[c+1];
                    *(__half2*)(Mnext + (size_t)rl*128 + c) =
                        __floats2half2_rn(fmaxf(acc2[i][j][0]+b0,0.f), fmaxf(acc2[i][j][1]+b1,0.f));
                    *(__half2*)(Mnext + (size_t)(rl+8)*128 + c) =
                        __floats2half2_rn(fmaxf(acc2[i][j][2]+b0,0.f), fmaxf(acc2[i][j][3]+b1,0.f));
                }
            }
            tgt += CH;
            g_arrive(ctr);
        }

        // ---- out-write from Y held in acc (off the publish path) ----
        #pragma unroll
        for (int i = 0; i < 2; ++i) {
            const int rl = r0 + wg*64 + wm*32 + i*16 + g;
            #pragma unroll
            for (int j = 0; j < 4; ++j) {
                const int c = wn*32 + j*8 + t*2;
                const size_t nlo = (size_t)l*PP + rl, nhi = nlo + 8;
                *(float2*)(out + nlo*256 + cofs + c) = make_float2(acc[i][j][0], acc[i][j][1]);
                *(float2*)(out + nhi*256 + cofs + c) = make_float2(acc[i][j][2], acc[i][j][3]);
            }
        }

        if (!last) g_wait(ctr, tgt);
    }
}

// ---------------- launch ----------------
extern "C" void kernel_launch(void* const* d_in, const int* in_sizes, int n_in,
                              void* d_out, int out_size) {
    const float* x       = (const float*)d_in[0];
    const int*   src     = (const int*)  d_in[1];
    const float* nt_w1   = (const float*)d_in[2];
    const float* nt_b1   = (const float*)d_in[3];
    const float* nt_w2   = (const float*)d_in[4];
    const float* nt_b2   = (const float*)d_in[5];
    const float* f_pre_w = (const float*)d_in[6];
    const float* f_pre_b = (const float*)d_in[7];
    const float* f_upd_w = (const float*)d_in[8];
    const float* f_upd_b = (const float*)d_in[9];
    const float* b_pre_w = (const float*)d_in[10];
    const float* b_pre_b = (const float*)d_in[11];
    const float* b_upd_w = (const float*)d_in[12];
    const float* b_upd_b = (const float*)d_in[13];
    float* out = (float*)d_out;

    void* p_cnt;
    cudaGetSymbolAddress(&p_cnt, g_cnt);

    cudaFuncSetAttribute(mega_kernel, cudaFuncAttributeMaxDynamicSharedMemorySize, CH_SMEM);

    cudaMemsetAsync(p_cnt, 0, (size_t)LEVE*PP*sizeof(int));
    prep_kernel<<<6 + CNTB, 256>>>(f_pre_w, f_upd_w, b_pre_w, b_upd_w, nt_w1, nt_w2, src);
    mega_kernel<<<2*CH, 512, CH_SMEM>>>(out, x, src,
        nt_b1, nt_b2, f_pre_b, f_upd_b, b_pre_b, b_upd_b);
}